// round 5
// baseline (speedup 1.0000x reference)
#include <cuda_runtime.h>
#include <cuda_fp16.h>
#include <math.h>
#include <stdint.h>

// Problem shapes (fixed)
#define Bq 2
#define Nq 2048
#define Dq 1024
#define Eq 2048
#define Fq 4096
#define Mq (Bq*Nq)   // 4096 tokens

// ---------------- device scratch (no cudaMalloc allowed) ----------------
__device__ __align__(1024) __half g_xn  [(size_t)Mq*Dq];
__device__ __align__(1024) __half g_Q   [(size_t)Mq*Eq];
__device__ __align__(1024) __half g_K   [(size_t)Mq*Eq];
__device__ __align__(1024) __half g_V   [(size_t)Mq*Eq];
__device__ __align__(1024) __half g_Vt  [(size_t)Mq*Eq];
__device__ __align__(1024) __half g_P   [(size_t)Bq*Nq*Nq];
__device__ __align__(1024) float  g_den [Mq];
__device__ __align__(1024) __half g_attn[(size_t)Mq*Eq];
__device__ __align__(1024) float  g_x1  [(size_t)Mq*Dq];
__device__ __align__(1024) __half g_xn2 [(size_t)Mq*Dq];
__device__ __align__(1024) __half g_h   [(size_t)Mq*Fq];
__device__ __align__(1024) __half g_qT  [(size_t)Dq*Eq];
__device__ __align__(1024) __half g_kT  [(size_t)Dq*Eq];
__device__ __align__(1024) __half g_vT  [(size_t)Dq*Eq];
__device__ __align__(1024) __half g_oT  [(size_t)Dq*Eq];
__device__ __align__(1024) __half g_w1T [(size_t)Dq*Fq];
__device__ __align__(1024) __half g_w2T [(size_t)Dq*Fq];

// ---------------- helpers ----------------
__device__ __forceinline__ uint32_t smem_u32(const void* p) {
    uint32_t a;
    asm("{ .reg .u64 t; cvta.to.shared.u64 t, %1; cvt.u32.u64 %0, t; }" : "=r"(a) : "l"(p));
    return a;
}
__device__ __forceinline__ void cp16(uint32_t dst, const void* src) {
    asm volatile("cp.async.cg.shared.global [%0], [%1], 16;" :: "r"(dst), "l"(src) : "memory");
}
#define CP_COMMIT() asm volatile("cp.async.commit_group;" ::: "memory")
#define CP_WAIT1()  asm volatile("cp.async.wait_group 1;" ::: "memory")

__device__ __forceinline__ void ldsm4(uint32_t (&r)[4], uint32_t addr) {
    asm volatile("ldmatrix.sync.aligned.m8n8.x4.shared.b16 {%0,%1,%2,%3}, [%4];"
                 : "=r"(r[0]), "=r"(r[1]), "=r"(r[2]), "=r"(r[3]) : "r"(addr));
}
__device__ __forceinline__ void mma_f16(float (&c)[4], const uint32_t (&a)[4],
                                        uint32_t b0, uint32_t b1) {
    asm volatile("mma.sync.aligned.m16n8k16.row.col.f32.f16.f16.f32 "
                 "{%0,%1,%2,%3}, {%4,%5,%6,%7}, {%8,%9}, {%0,%1,%2,%3};"
                 : "+f"(c[0]), "+f"(c[1]), "+f"(c[2]), "+f"(c[3])
                 : "r"(a[0]), "r"(a[1]), "r"(a[2]), "r"(a[3]), "r"(b0), "r"(b1));
}
__device__ __forceinline__ void st2(float* p, float a, float b) {
    *reinterpret_cast<float2*>(p) = make_float2(a, b);
}
__device__ __forceinline__ void st2(__half* p, float a, float b) {
    *reinterpret_cast<__half2*>(p) = __floats2half2_rn(a, b);
}
__device__ __forceinline__ float ldf(const float* p)  { return *p; }
__device__ __forceinline__ float ldf(const __half* p) { return __half2float(*p); }

// ---------------- elementwise kernels ----------------
__global__ __launch_bounds__(256)
void ln_kernel(const float* __restrict__ x, const float* __restrict__ g,
               const float* __restrict__ b, __half* __restrict__ y)
{
    int row = blockIdx.x;
    int t = threadIdx.x;
    const float4* xr = reinterpret_cast<const float4*>(x + (size_t)row * Dq);
    float4 v = xr[t];
    float s  = v.x + v.y + v.z + v.w;
    float s2 = v.x*v.x + v.y*v.y + v.z*v.z + v.w*v.w;
    __shared__ float rs[8], rs2[8];
    #pragma unroll
    for (int o = 16; o > 0; o >>= 1) {
        s  += __shfl_down_sync(0xffffffffu, s,  o);
        s2 += __shfl_down_sync(0xffffffffu, s2, o);
    }
    if ((t & 31) == 0) { rs[t >> 5] = s; rs2[t >> 5] = s2; }
    __syncthreads();
    float ssum = 0.f, ssum2 = 0.f;
    #pragma unroll
    for (int i = 0; i < 8; i++) { ssum += rs[i]; ssum2 += rs2[i]; }
    float mu   = ssum * (1.0f / Dq);
    float var  = ssum2 * (1.0f / Dq) - mu * mu;
    float rstd = rsqrtf(var + 1e-5f);
    float4 gg = reinterpret_cast<const float4*>(g)[t];
    float4 bb = reinterpret_cast<const float4*>(b)[t];
    __half2 h01 = __floats2half2_rn((v.x - mu) * rstd * gg.x + bb.x,
                                    (v.y - mu) * rstd * gg.y + bb.y);
    __half2 h23 = __floats2half2_rn((v.z - mu) * rstd * gg.z + bb.z,
                                    (v.w - mu) * rstd * gg.w + bb.w);
    __half2* yp = reinterpret_cast<__half2*>(y + (size_t)row * Dq);
    yp[t * 2]     = h01;
    yp[t * 2 + 1] = h23;
}

__global__ void den_init(float* den) { den[blockIdx.x * 256 + threadIdx.x] = 1e-6f; }

// in [R,C] -> out [C,R], batched in z
template<typename Ti, typename To>
__global__ __launch_bounds__(256)
void tr_kernel(const Ti* __restrict__ in, To* __restrict__ out,
               int R, int C, long long sIn, long long sOut)
{
    __shared__ float t[32][33];
    const Ti* ib = in  + (size_t)blockIdx.z * sIn;
    To*       ob = out + (size_t)blockIdx.z * sOut;
    int c = blockIdx.x * 32 + threadIdx.x;
    int r = blockIdx.y * 32 + threadIdx.y;
    #pragma unroll
    for (int dy = 0; dy < 32; dy += 8)
        t[threadIdx.y + dy][threadIdx.x] = ldf(&ib[(size_t)(r + dy) * C + c]);
    __syncthreads();
    int c2 = blockIdx.y * 32 + threadIdx.x;
    int r2 = blockIdx.x * 32 + threadIdx.y;
    #pragma unroll
    for (int dy = 0; dy < 32; dy += 8)
        ob[(size_t)(r2 + dy) * R + c2] = (To)t[threadIdx.x][threadIdx.y + dy];
}

// ---------------- fp16 mma.sync GEMM: 128x128 CTA, 4 warps (2Mx2N), warp 64x64 ----------------
// 2-stage cp.async pipeline (32KB/stage, 64KB total) -> 2 CTAs/SM.
__device__ __forceinline__ float gelu_exact(float v) {
    return 0.5f * v * (1.0f + erff(v * 0.70710678118654752f));
}
enum { EPI_BIAS = 0, EPI_FEAT = 1, EPI_GELU = 2, EPI_BIAS_RES = 3, EPI_DIV = 4, EPI_SCORE = 5 };
// CM: 0 none, 1 score-causal (skip upper tiles, mask, rowsum->den), 2 PV (K limited to r0+128)

#define MM_SMEM (2 * 32768 + 1024)

template<int EPI, int CM, typename OutT>
__global__ __launch_bounds__(128, 2)
void mm_kernel(const __half* __restrict__ A, const __half* __restrict__ Bm, OutT* __restrict__ C,
               int ldA, int ldB, int ldC, int Kdim,
               long long sA, long long sB, long long sC,
               const float* __restrict__ bias,
               const float* __restrict__ res, long long sRes,
               float* __restrict__ den, int denB)
{
    int bz = blockIdx.z;
    int r0 = blockIdx.y * 128, c0 = blockIdx.x * 128;
    if (CM == 1 && c0 > r0) return;
    const int keff = (CM == 2) ? (r0 + 128) : Kdim;
    const int nc = keff >> 6;                 // 64-half K chunks (128B per row); nc >= 2 always

    const __half* Ab = A  + (size_t)bz * sA;
    const __half* Bb = Bm + (size_t)bz * sB;
    OutT*         Cb = C  + (size_t)bz * sC;

    extern __shared__ char dsm[];
    uint32_t s0 = (smem_u32(dsm) + 1023u) & ~1023u;   // stage s: A at s*32768, B at +16384

    int tid = threadIdx.x;

    // ---- loader: each thread owns one row of A and one row of B (8 cp16 each) ----
    int lm = tid;                         // row 0..127
    const __half* gA = Ab + (size_t)(r0 + lm) * ldA;
    const __half* gB = Bb + (size_t)(c0 + lm) * ldB;
    uint32_t swb = (uint32_t)lm * 128u;
    int lr7 = lm & 7;

    // prologue: chunks 0,1 -> stages 0,1
    #pragma unroll
    for (int j = 0; j < 2; j++) {
        uint32_t aB = s0 + j * 32768, bB = aB + 16384;
        #pragma unroll
        for (int i = 0; i < 8; i++) {
            uint32_t sw = swb + (uint32_t)((i ^ lr7) << 4);
            cp16(aB + sw, gA + j * 64 + i * 8);
            cp16(bB + sw, gB + j * 64 + i * 8);
        }
        CP_COMMIT();
    }

    // ---- fragment address bases ----
    int lane = tid & 31;
    int wm = (tid >> 5) & 1;           // 2 warps in M (64 rows each)
    int wn = (tid >> 6) & 1;           // 2 warps in N (64 cols each)
    int aRow = wm * 64 + (lane & 15);  // + mt*16
    int aHalf = lane >> 4;
    int bg = lane >> 3;
    int bRow = wn * 64 + ((bg >> 1) * 8) + (lane & 7);  // + np*16
    int bHalf = bg & 1;
    uint32_t aOff = (uint32_t)aRow * 128u;
    uint32_t bOff = (uint32_t)bRow * 128u;
    int aR7 = aRow & 7, bR7 = bRow & 7;

    float c[4][8][4];
    #pragma unroll
    for (int mt = 0; mt < 4; mt++)
        #pragma unroll
        for (int nt = 0; nt < 8; nt++)
            #pragma unroll
            for (int k = 0; k < 4; k++) c[mt][nt][k] = 0.f;

    for (int i = 0; i < nc; i++) {
        int s = i & 1;
        CP_WAIT1();
        __syncthreads();
        uint32_t aB = s0 + s * 32768, bB = aB + 16384;
        #pragma unroll
        for (int ks = 0; ks < 4; ks++) {      // 4 k16 steps per 64-half chunk
            uint32_t a[4][4];
            #pragma unroll
            for (int mt = 0; mt < 4; mt++) {
                uint32_t ad = aB + aOff + (uint32_t)(mt * 16 * 128)
                            + (uint32_t)(((ks * 2 + aHalf) ^ aR7) << 4);
                ldsm4(a[mt], ad);
            }
            uint32_t b[16];
            #pragma unroll
            for (int np = 0; np < 4; np++) {
                uint32_t bd = bB + bOff + (uint32_t)(np * 16 * 128)
                            + (uint32_t)(((ks * 2 + bHalf) ^ bR7) << 4);
                uint32_t r[4];
                ldsm4(r, bd);
                b[np*4+0]=r[0]; b[np*4+1]=r[1]; b[np*4+2]=r[2]; b[np*4+3]=r[3];
            }
            #pragma unroll
            for (int mt = 0; mt < 4; mt++)
                #pragma unroll
                for (int nt = 0; nt < 8; nt++)
                    mma_f16(c[mt][nt], a[mt], b[nt*2], b[nt*2+1]);
        }
        __syncthreads();
        if (i + 2 < nc) {
            int j = i + 2;
            uint32_t aB2 = s0 + s * 32768, bB2 = aB2 + 16384;
            #pragma unroll
            for (int ii = 0; ii < 8; ii++) {
                uint32_t sw = swb + (uint32_t)((ii ^ lr7) << 4);
                cp16(aB2 + sw, gA + j * 64 + ii * 8);
                cp16(bB2 + sw, gB + j * 64 + ii * 8);
            }
        }
        CP_COMMIT();
    }

    // ---- epilogue ----
    int g4 = lane >> 2, q4 = lane & 3;
    #pragma unroll
    for (int mt = 0; mt < 4; mt++) {
        int row0 = r0 + wm * 64 + mt * 16 + g4;
        int row1 = row0 + 8;
        float d0 = 1.f, d1 = 1.f;
        if (EPI == EPI_DIV) {
            d0 = 1.0f / den[(size_t)bz * denB + row0];
            d1 = 1.0f / den[(size_t)bz * denB + row1];
        }
        float rs0 = 0.f, rs1 = 0.f;
        #pragma unroll
        for (int nt = 0; nt < 8; nt++) {
            int col = c0 + wn * 64 + nt * 8 + q4 * 2;
            float v0 = c[mt][nt][0], v1 = c[mt][nt][1];
            float v2 = c[mt][nt][2], v3 = c[mt][nt][3];
            if (EPI == EPI_BIAS || EPI == EPI_FEAT || EPI == EPI_GELU || EPI == EPI_BIAS_RES) {
                float2 bv = *reinterpret_cast<const float2*>(bias + col);
                v0 += bv.x; v1 += bv.y; v2 += bv.x; v3 += bv.y;
            }
            if (EPI == EPI_FEAT) {
                v0 = (v0 > 0.f) ? (v0 + 1.f) : expf(v0);
                v1 = (v1 > 0.f) ? (v1 + 1.f) : expf(v1);
                v2 = (v2 > 0.f) ? (v2 + 1.f) : expf(v2);
                v3 = (v3 > 0.f) ? (v3 + 1.f) : expf(v3);
            }
            if (EPI == EPI_GELU) {
                v0 = gelu_exact(v0); v1 = gelu_exact(v1);
                v2 = gelu_exact(v2); v3 = gelu_exact(v3);
            }
            if (EPI == EPI_BIAS_RES) {
                const float* rp0 = res + (size_t)bz * sRes + (size_t)row0 * ldC + col;
                const float* rp1 = res + (size_t)bz * sRes + (size_t)row1 * ldC + col;
                float2 r0v = *reinterpret_cast<const float2*>(rp0);
                float2 r1v = *reinterpret_cast<const float2*>(rp1);
                v0 += r0v.x; v1 += r0v.y; v2 += r1v.x; v3 += r1v.y;
            }
            if (EPI == EPI_DIV) {
                v0 *= d0; v1 *= d0; v2 *= d1; v3 *= d1;
            }
            if (EPI == EPI_SCORE) {
                if (col     > row0) v0 = 0.f;
                if (col + 1 > row0) v1 = 0.f;
                if (col     > row1) v2 = 0.f;
                if (col + 1 > row1) v3 = 0.f;
                rs0 += v0 + v1; rs1 += v2 + v3;
            }
            st2(Cb + (size_t)row0 * ldC + col, v0, v1);
            st2(Cb + (size_t)row1 * ldC + col, v2, v3);
        }
        if (EPI == EPI_SCORE) {
            atomicAdd(&den[(size_t)bz * denB + row0], rs0);
            atomicAdd(&den[(size_t)bz * denB + row1], rs1);
        }
    }
}

// ---------------- launch ----------------
extern "C" void kernel_launch(void* const* d_in, const int* in_sizes, int n_in,
                              void* d_out, int out_size)
{
    const float* x     = (const float*)d_in[0];
    const float* q_w   = (const float*)d_in[1];
    const float* q_b   = (const float*)d_in[2];
    const float* k_w   = (const float*)d_in[3];
    const float* k_b   = (const float*)d_in[4];
    const float* v_w   = (const float*)d_in[5];
    const float* v_b   = (const float*)d_in[6];
    const float* o_w   = (const float*)d_in[7];
    const float* o_b   = (const float*)d_in[8];
    const float* ln1_g = (const float*)d_in[9];
    const float* ln1_b = (const float*)d_in[10];
    const float* ln2_g = (const float*)d_in[11];
    const float* ln2_b = (const float*)d_in[12];
    const float* w1    = (const float*)d_in[13];
    const float* b1    = (const float*)d_in[14];
    const float* w2    = (const float*)d_in[15];
    const float* b2    = (const float*)d_in[16];
    float* out = (float*)d_out;

    __half *xn, *Qp, *Kp, *Vp, *Vt, *Pp, *attn, *xn2, *h;
    __half *qT, *kT, *vT, *oT, *w1T, *w2T;
    float *den, *x1;
    cudaGetSymbolAddress((void**)&xn,   g_xn);
    cudaGetSymbolAddress((void**)&Qp,   g_Q);
    cudaGetSymbolAddress((void**)&Kp,   g_K);
    cudaGetSymbolAddress((void**)&Vp,   g_V);
    cudaGetSymbolAddress((void**)&Vt,   g_Vt);
    cudaGetSymbolAddress((void**)&Pp,   g_P);
    cudaGetSymbolAddress((void**)&den,  g_den);
    cudaGetSymbolAddress((void**)&attn, g_attn);
    cudaGetSymbolAddress((void**)&x1,   g_x1);
    cudaGetSymbolAddress((void**)&xn2,  g_xn2);
    cudaGetSymbolAddress((void**)&h,    g_h);
    cudaGetSymbolAddress((void**)&qT,   g_qT);
    cudaGetSymbolAddress((void**)&kT,   g_kT);
    cudaGetSymbolAddress((void**)&vT,   g_vT);
    cudaGetSymbolAddress((void**)&oT,   g_oT);
    cudaGetSymbolAddress((void**)&w1T,  g_w1T);
    cudaGetSymbolAddress((void**)&w2T,  g_w2T);

    cudaFuncSetAttribute(mm_kernel<EPI_FEAT, 0, __half>,    cudaFuncAttributeMaxDynamicSharedMemorySize, MM_SMEM);
    cudaFuncSetAttribute(mm_kernel<EPI_BIAS, 0, __half>,    cudaFuncAttributeMaxDynamicSharedMemorySize, MM_SMEM);
    cudaFuncSetAttribute(mm_kernel<EPI_SCORE, 1, __half>,   cudaFuncAttributeMaxDynamicSharedMemorySize, MM_SMEM);
    cudaFuncSetAttribute(mm_kernel<EPI_DIV, 2, __half>,     cudaFuncAttributeMaxDynamicSharedMemorySize, MM_SMEM);
    cudaFuncSetAttribute(mm_kernel<EPI_BIAS_RES, 0, float>, cudaFuncAttributeMaxDynamicSharedMemorySize, MM_SMEM);
    cudaFuncSetAttribute(mm_kernel<EPI_GELU, 0, __half>,    cudaFuncAttributeMaxDynamicSharedMemorySize, MM_SMEM);

    dim3 tb(32, 8);

    // LN1 -> fp16
    ln_kernel<<<Mq, 256>>>(x, ln1_g, ln1_b, xn);

    // weight transposes -> [N, K] K-major fp16
    tr_kernel<float, __half><<<dim3(Eq/32, Dq/32, 1), tb>>>(q_w, qT, Dq, Eq, 0, 0);
    tr_kernel<float, __half><<<dim3(Eq/32, Dq/32, 1), tb>>>(k_w, kT, Dq, Eq, 0, 0);
    tr_kernel<float, __half><<<dim3(Eq/32, Dq/32, 1), tb>>>(v_w, vT, Dq, Eq, 0, 0);
    tr_kernel<float, __half><<<dim3(Dq/32, Eq/32, 1), tb>>>(o_w, oT, Eq, Dq, 0, 0);
    tr_kernel<float, __half><<<dim3(Fq/32, Dq/32, 1), tb>>>(w1, w1T, Dq, Fq, 0, 0);
    tr_kernel<float, __half><<<dim3(Dq/32, Fq/32, 1), tb>>>(w2, w2T, Fq, Dq, 0, 0);

    // Q/K/V projections
    mm_kernel<EPI_FEAT, 0, __half><<<dim3(Eq/128, Mq/128, 1), 128, MM_SMEM>>>(
        xn, qT, Qp, Dq, Dq, Eq, Dq, 0, 0, 0, q_b, nullptr, 0, nullptr, 0);
    mm_kernel<EPI_FEAT, 0, __half><<<dim3(Eq/128, Mq/128, 1), 128, MM_SMEM>>>(
        xn, kT, Kp, Dq, Dq, Eq, Dq, 0, 0, 0, k_b, nullptr, 0, nullptr, 0);
    mm_kernel<EPI_BIAS, 0, __half><<<dim3(Eq/128, Mq/128, 1), 128, MM_SMEM>>>(
        xn, vT, Vp, Dq, Dq, Eq, Dq, 0, 0, 0, v_b, nullptr, 0, nullptr, 0);

    // V^T per batch: [Nq, Eq] -> [Eq, Nq]
    tr_kernel<__half, __half><<<dim3(Eq/32, Nq/32, Bq), tb>>>(Vp, Vt, Nq, Eq,
        (long long)Nq * Eq, (long long)Nq * Eq);

    // scores: P = tril(Q K^T); den = rowsum + 1e-6
    den_init<<<Mq/256, 256>>>(den);
    mm_kernel<EPI_SCORE, 1, __half><<<dim3(Nq/128, Nq/128, Bq), 128, MM_SMEM>>>(
        Qp, Kp, Pp, Eq, Eq, Nq, Eq,
        (long long)Nq * Eq, (long long)Nq * Eq, (long long)Nq * Nq,
        nullptr, nullptr, 0, den, Nq);

    // attn = (P @ V) / den  (B operand = V^T, K limited per tile row)
    mm_kernel<EPI_DIV, 2, __half><<<dim3(Eq/128, Nq/128, Bq), 128, MM_SMEM>>>(
        Pp, Vt, attn, Nq, Nq, Eq, Nq,
        (long long)Nq * Nq, (long long)Nq * Eq, (long long)Nq * Eq,
        nullptr, nullptr, 0, den, Nq);

    // output projection + residual (fp32 out)
    mm_kernel<EPI_BIAS_RES, 0, float><<<dim3(Dq/128, Mq/128, 1), 128, MM_SMEM>>>(
        attn, oT, x1, Eq, Eq, Dq, Eq, 0, 0, 0, o_b, x, 0, nullptr, 0);

    // LN2 + FFN
    ln_kernel<<<Mq, 256>>>(x1, ln2_g, ln2_b, xn2);
    mm_kernel<EPI_GELU, 0, __half><<<dim3(Fq/128, Mq/128, 1), 128, MM_SMEM>>>(
        xn2, w1T, h, Dq, Dq, Fq, Dq, 0, 0, 0, b1, nullptr, 0, nullptr, 0);
    mm_kernel<EPI_BIAS_RES, 0, float><<<dim3(Dq/128, Mq/128, 1), 128, MM_SMEM>>>(
        h, w2T, out, Fq, Fq, Dq, Fq, 0, 0, 0, b2, x1, 0, nullptr, 0);
}

// round 6
// speedup vs baseline: 1.4040x; 1.4040x over previous
#include <cuda_runtime.h>
#include <cuda_fp16.h>
#include <math.h>
#include <stdint.h>

// Problem shapes (fixed)
#define Bq 2
#define Nq 2048
#define Dq 1024
#define Eq 2048
#define Fq 4096
#define Mq (Bq*Nq)   // 4096 tokens

// ---------------- device scratch (no cudaMalloc allowed) ----------------
__device__ __align__(1024) __half g_xn   [(size_t)Mq*Dq];
__device__ __align__(1024) __half g_Q    [(size_t)Mq*Eq];
__device__ __align__(1024) __half g_K    [(size_t)Mq*Eq];
__device__ __align__(1024) __half g_V    [(size_t)Mq*Eq];
__device__ __align__(1024) __half g_Vt   [(size_t)Mq*Eq];
__device__ __align__(1024) __half g_P    [(size_t)Bq*Nq*Nq];
__device__ __align__(1024) float  g_den  [Mq];
__device__ __align__(1024) __half g_attn [(size_t)Mq*Eq];
__device__ __align__(1024) float  g_x1   [(size_t)Mq*Dq];
__device__ __align__(1024) __half g_xn2  [(size_t)Mq*Dq];
__device__ __align__(1024) __half g_h    [(size_t)Mq*Fq];
__device__ __align__(1024) __half g_qkvT [(size_t)3*Eq*Dq];  // rows: [0,E)=qT, [E,2E)=kT, [2E,3E)=vT
__device__ __align__(1024) __half g_oT   [(size_t)Dq*Eq];
__device__ __align__(1024) __half g_w1T  [(size_t)Dq*Fq];
__device__ __align__(1024) __half g_w2T  [(size_t)Dq*Fq];

// ---------------- helpers ----------------
__device__ __forceinline__ uint32_t smem_u32(const void* p) {
    uint32_t a;
    asm("{ .reg .u64 t; cvta.to.shared.u64 t, %1; cvt.u32.u64 %0, t; }" : "=r"(a) : "l"(p));
    return a;
}
__device__ __forceinline__ void cp16(uint32_t dst, const void* src) {
    asm volatile("cp.async.cg.shared.global [%0], [%1], 16;" :: "r"(dst), "l"(src) : "memory");
}
#define CP_COMMIT() asm volatile("cp.async.commit_group;" ::: "memory")
#define CP_WAIT2()  asm volatile("cp.async.wait_group 2;" ::: "memory")

__device__ __forceinline__ void ldsm4(uint32_t (&r)[4], uint32_t addr) {
    asm volatile("ldmatrix.sync.aligned.m8n8.x4.shared.b16 {%0,%1,%2,%3}, [%4];"
                 : "=r"(r[0]), "=r"(r[1]), "=r"(r[2]), "=r"(r[3]) : "r"(addr));
}
__device__ __forceinline__ void mma_f16(float (&c)[4], const uint32_t (&a)[4],
                                        uint32_t b0, uint32_t b1) {
    asm volatile("mma.sync.aligned.m16n8k16.row.col.f32.f16.f16.f32 "
                 "{%0,%1,%2,%3}, {%4,%5,%6,%7}, {%8,%9}, {%0,%1,%2,%3};"
                 : "+f"(c[0]), "+f"(c[1]), "+f"(c[2]), "+f"(c[3])
                 : "r"(a[0]), "r"(a[1]), "r"(a[2]), "r"(a[3]), "r"(b0), "r"(b1));
}
__device__ __forceinline__ void st2(float* p, float a, float b) {
    *reinterpret_cast<float2*>(p) = make_float2(a, b);
}
__device__ __forceinline__ void st2(__half* p, float a, float b) {
    *reinterpret_cast<__half2*>(p) = __floats2half2_rn(a, b);
}
__device__ __forceinline__ float ldf(const float* p)  { return *p; }
__device__ __forceinline__ float ldf(const __half* p) { return __half2float(*p); }

// ---------------- elementwise kernels ----------------
__global__ __launch_bounds__(256)
void ln_kernel(const float* __restrict__ x, const float* __restrict__ g,
               const float* __restrict__ b, __half* __restrict__ y)
{
    int row = blockIdx.x;
    int t = threadIdx.x;
    const float4* xr = reinterpret_cast<const float4*>(x + (size_t)row * Dq);
    float4 v = xr[t];
    float s  = v.x + v.y + v.z + v.w;
    float s2 = v.x*v.x + v.y*v.y + v.z*v.z + v.w*v.w;
    __shared__ float rs[8], rs2[8];
    #pragma unroll
    for (int o = 16; o > 0; o >>= 1) {
        s  += __shfl_down_sync(0xffffffffu, s,  o);
        s2 += __shfl_down_sync(0xffffffffu, s2, o);
    }
    if ((t & 31) == 0) { rs[t >> 5] = s; rs2[t >> 5] = s2; }
    __syncthreads();
    float ssum = 0.f, ssum2 = 0.f;
    #pragma unroll
    for (int i = 0; i < 8; i++) { ssum += rs[i]; ssum2 += rs2[i]; }
    float mu   = ssum * (1.0f / Dq);
    float var  = ssum2 * (1.0f / Dq) - mu * mu;
    float rstd = rsqrtf(var + 1e-5f);
    float4 gg = reinterpret_cast<const float4*>(g)[t];
    float4 bb = reinterpret_cast<const float4*>(b)[t];
    __half2 h01 = __floats2half2_rn((v.x - mu) * rstd * gg.x + bb.x,
                                    (v.y - mu) * rstd * gg.y + bb.y);
    __half2 h23 = __floats2half2_rn((v.z - mu) * rstd * gg.z + bb.z,
                                    (v.w - mu) * rstd * gg.w + bb.w);
    __half2* yp = reinterpret_cast<__half2*>(y + (size_t)row * Dq);
    yp[t * 2]     = h01;
    yp[t * 2 + 1] = h23;
}

__global__ void den_init(float* den) { den[blockIdx.x * 256 + threadIdx.x] = 1e-6f; }

// in [R,C] -> out [C,R], batched in z
template<typename Ti, typename To>
__global__ __launch_bounds__(256)
void tr_kernel(const Ti* __restrict__ in, To* __restrict__ out,
               int R, int C, long long sIn, long long sOut)
{
    __shared__ float t[32][33];
    const Ti* ib = in  + (size_t)blockIdx.z * sIn;
    To*       ob = out + (size_t)blockIdx.z * sOut;
    int c = blockIdx.x * 32 + threadIdx.x;
    int r = blockIdx.y * 32 + threadIdx.y;
    #pragma unroll
    for (int dy = 0; dy < 32; dy += 8)
        t[threadIdx.y + dy][threadIdx.x] = ldf(&ib[(size_t)(r + dy) * C + c]);
    __syncthreads();
    int c2 = blockIdx.y * 32 + threadIdx.x;
    int r2 = blockIdx.x * 32 + threadIdx.y;
    #pragma unroll
    for (int dy = 0; dy < 32; dy += 8)
        ob[(size_t)(r2 + dy) * R + c2] = (To)t[threadIdx.x][threadIdx.y + dy];
}

// three [Dq,Eq] fp32 sources -> one [3*Eq, Dq] fp16 dest (z picks source)
__global__ __launch_bounds__(256)
void tr_qkv_kernel(const float* __restrict__ s0, const float* __restrict__ s1,
                   const float* __restrict__ s2, __half* __restrict__ out)
{
    __shared__ float t[32][33];
    const float* ib = (blockIdx.z == 0) ? s0 : (blockIdx.z == 1) ? s1 : s2;
    __half* ob = out + (size_t)blockIdx.z * Eq * Dq;
    int c = blockIdx.x * 32 + threadIdx.x;
    int r = blockIdx.y * 32 + threadIdx.y;
    #pragma unroll
    for (int dy = 0; dy < 32; dy += 8)
        t[threadIdx.y + dy][threadIdx.x] = ib[(size_t)(r + dy) * Eq + c];
    __syncthreads();
    int c2 = blockIdx.y * 32 + threadIdx.x;
    int r2 = blockIdx.x * 32 + threadIdx.y;
    #pragma unroll
    for (int dy = 0; dy < 32; dy += 8)
        ob[(size_t)(r2 + dy) * Dq + c2] = (__half)t[threadIdx.x][threadIdx.y + dy];
}

// ---------------- fp16 mma.sync GEMM: 128x128 CTA, 8 warps (2Mx4N), warp 64x32 ----------------
// 4-stage cp.async pipeline (32KB/stage, 128KB), single barrier per k-chunk.
__device__ __forceinline__ float gelu_exact(float v) {
    return 0.5f * v * (1.0f + erff(v * 0.70710678118654752f));
}
enum { EPI_BIAS = 0, EPI_FEAT = 1, EPI_GELU = 2, EPI_BIAS_RES = 3, EPI_DIV = 4, EPI_SCORE = 5, EPI_QKV = 6 };
// CM: 0 none, 1 score-causal (skip upper tiles, mask, rowsum->den), 2 PV (K limited to r0+128)

#define MM_SMEM (4 * 32768 + 1024)

template<int EPI, int CM, typename OutT>
__global__ __launch_bounds__(256, 1)
void mm_kernel(const __half* __restrict__ A, const __half* __restrict__ Bm, OutT* __restrict__ C,
               int ldA, int ldB, int ldC, int Kdim,
               long long sA, long long sB, long long sC,
               const float* __restrict__ bias,
               const float* __restrict__ res, long long sRes,
               float* __restrict__ den, int denB,
               const float* __restrict__ bias2 = nullptr,
               const float* __restrict__ bias3 = nullptr,
               OutT* __restrict__ C2 = nullptr,
               OutT* __restrict__ C3 = nullptr)
{
    int bz = blockIdx.z;
    int r0 = blockIdx.y * 128, c0 = blockIdx.x * 128;
    if (CM == 1 && c0 > r0) return;
    const int keff = (CM == 2) ? (r0 + 128) : Kdim;
    const int nc = keff >> 6;                 // 64-half K chunks (128B per row); nc >= 2 always

    const __half* Ab = A  + (size_t)bz * sA;
    const __half* Bb = Bm + (size_t)bz * sB;
    OutT*         Cb = C  + (size_t)bz * sC;

    extern __shared__ char dsm[];
    uint32_t s0 = (smem_u32(dsm) + 1023u) & ~1023u;   // stage s: A at s*32768, B at +16384

    int tid = threadIdx.x;

    // ---- loader: each thread does 4 A + 4 B cp.async of 16B per chunk ----
    int lm = tid >> 1;                 // row 0..127
    int cbase = (tid & 1) * 4;         // 16B-chunk base within 8 chunks per 128B row
    const __half* gA = Ab + (size_t)(r0 + lm) * ldA + cbase * 8;
    const __half* gB = Bb + (size_t)(c0 + lm) * ldB + cbase * 8;
    uint32_t sw[4];
    #pragma unroll
    for (int i = 0; i < 4; i++)
        sw[i] = (uint32_t)lm * 128u + (uint32_t)(((cbase + i) ^ (lm & 7)) << 4);

    // prologue: chunks 0..2 -> stages 0..2
    #pragma unroll
    for (int j = 0; j < 3; j++) {
        uint32_t aB = s0 + j * 32768, bB = aB + 16384;
        #pragma unroll
        for (int i = 0; i < 4; i++) {
            cp16(aB + sw[i], gA + j * 64 + i * 8);
            cp16(bB + sw[i], gB + j * 64 + i * 8);
        }
        CP_COMMIT();
    }

    // ---- fragment address bases ----
    int lane = tid & 31;
    int wm = (tid >> 5) & 1;           // 2 warps in M (64 rows each)
    int wn = tid >> 6;                 // 4 warps in N (32 cols each)
    int aRow = wm * 64 + (lane & 15);  // + mt*16
    int aHalf = lane >> 4;
    int bg = lane >> 3;
    int bRow = wn * 32 + ((bg >> 1) * 8) + (lane & 7);
    int bHalf = bg & 1;
    uint32_t aOff = (uint32_t)aRow * 128u;
    uint32_t bOff = (uint32_t)bRow * 128u;
    int aR7 = aRow & 7, bR7 = bRow & 7;

    float c[4][4][4];
    #pragma unroll
    for (int mt = 0; mt < 4; mt++)
        #pragma unroll
        for (int nt = 0; nt < 4; nt++)
            #pragma unroll
            for (int k = 0; k < 4; k++) c[mt][nt][k] = 0.f;

    for (int i = 0; i < nc; i++) {
        int s = i & 3;
        CP_WAIT2();          // chunk i's group complete
        __syncthreads();     // data visible to all warps; stage (i+3)&3 fully consumed (iter i-1)
        {
            int j = i + 3;
            if (j < nc) {
                int st = j & 3;
                uint32_t aB2 = s0 + st * 32768, bB2 = aB2 + 16384;
                #pragma unroll
                for (int ii = 0; ii < 4; ii++) {
                    cp16(aB2 + sw[ii], gA + (size_t)j * 64 + ii * 8);
                    cp16(bB2 + sw[ii], gB + (size_t)j * 64 + ii * 8);
                }
            }
            CP_COMMIT();     // commit (possibly empty) to keep group counting aligned
        }
        uint32_t aB = s0 + s * 32768, bB = aB + 16384;
        #pragma unroll
        for (int ks = 0; ks < 4; ks++) {      // 4 k16 steps per 64-half chunk
            uint32_t a[4][4];
            #pragma unroll
            for (int mt = 0; mt < 4; mt++) {
                uint32_t ad = aB + aOff + (uint32_t)(mt * 16 * 128)
                            + (uint32_t)(((ks * 2 + aHalf) ^ aR7) << 4);
                ldsm4(a[mt], ad);
            }
            uint32_t b[8];
            #pragma unroll
            for (int np = 0; np < 2; np++) {
                uint32_t bd = bB + bOff + (uint32_t)(np * 16 * 128)
                            + (uint32_t)(((ks * 2 + bHalf) ^ bR7) << 4);
                uint32_t r[4];
                ldsm4(r, bd);
                b[np*4+0]=r[0]; b[np*4+1]=r[1]; b[np*4+2]=r[2]; b[np*4+3]=r[3];
            }
            #pragma unroll
            for (int mt = 0; mt < 4; mt++) {
                mma_f16(c[mt][0], a[mt], b[0], b[1]);
                mma_f16(c[mt][1], a[mt], b[2], b[3]);
                mma_f16(c[mt][2], a[mt], b[4], b[5]);
                mma_f16(c[mt][3], a[mt], b[6], b[7]);
            }
        }
    }

    // ---- epilogue ----
    // QKV fused: segment by CTA column tile (uniform per CTA)
    int seg = 0;
    const float* biasSel = bias;
    OutT* outSel = Cb;
    if (EPI == EPI_QKV) {
        seg = c0 >> 11;                            // 0:Q 1:K 2:V
        biasSel = (seg == 0) ? bias : (seg == 1) ? bias2 : bias3;
        outSel  = (seg == 0) ? C : (seg == 1) ? C2 : C3;
    }
    int cSub = (EPI == EPI_QKV) ? (c0 - (seg << 11)) : c0;

    int g4 = lane >> 2, q4 = lane & 3;
    #pragma unroll
    for (int mt = 0; mt < 4; mt++) {
        int row0 = r0 + wm * 64 + mt * 16 + g4;
        int row1 = row0 + 8;
        float d0 = 1.f, d1 = 1.f;
        if (EPI == EPI_DIV) {
            d0 = 1.0f / den[(size_t)bz * denB + row0];
            d1 = 1.0f / den[(size_t)bz * denB + row1];
        }
        float rs0 = 0.f, rs1 = 0.f;
        #pragma unroll
        for (int nt = 0; nt < 4; nt++) {
            int colL = cSub + wn * 32 + nt * 8 + q4 * 2;   // local col for bias/store
            int col  = c0 + wn * 32 + nt * 8 + q4 * 2;     // global col (mask)
            float v0 = c[mt][nt][0], v1 = c[mt][nt][1];
            float v2 = c[mt][nt][2], v3 = c[mt][nt][3];
            if (EPI == EPI_BIAS || EPI == EPI_FEAT || EPI == EPI_GELU ||
                EPI == EPI_BIAS_RES || EPI == EPI_QKV) {
                float2 bv = *reinterpret_cast<const float2*>(biasSel + colL);
                v0 += bv.x; v1 += bv.y; v2 += bv.x; v3 += bv.y;
            }
            if (EPI == EPI_FEAT || (EPI == EPI_QKV && seg < 2)) {
                v0 = (v0 > 0.f) ? (v0 + 1.f) : expf(v0);
                v1 = (v1 > 0.f) ? (v1 + 1.f) : expf(v1);
                v2 = (v2 > 0.f) ? (v2 + 1.f) : expf(v2);
                v3 = (v3 > 0.f) ? (v3 + 1.f) : expf(v3);
            }
            if (EPI == EPI_GELU) {
                v0 = gelu_exact(v0); v1 = gelu_exact(v1);
                v2 = gelu_exact(v2); v3 = gelu_exact(v3);
            }
            if (EPI == EPI_BIAS_RES) {
                const float* rp0 = res + (size_t)bz * sRes + (size_t)row0 * ldC + colL;
                const float* rp1 = res + (size_t)bz * sRes + (size_t)row1 * ldC + colL;
                float2 r0v = *reinterpret_cast<const float2*>(rp0);
                float2 r1v = *reinterpret_cast<const float2*>(rp1);
                v0 += r0v.x; v1 += r0v.y; v2 += r1v.x; v3 += r1v.y;
            }
            if (EPI == EPI_DIV) {
                v0 *= d0; v1 *= d0; v2 *= d1; v3 *= d1;
            }
            if (EPI == EPI_SCORE) {
                if (col     > row0) v0 = 0.f;
                if (col + 1 > row0) v1 = 0.f;
                if (col     > row1) v2 = 0.f;
                if (col + 1 > row1) v3 = 0.f;
                rs0 += v0 + v1; rs1 += v2 + v3;
            }
            st2(outSel + (size_t)row0 * ldC + colL, v0, v1);
            st2(outSel + (size_t)row1 * ldC + colL, v2, v3);
        }
        if (EPI == EPI_SCORE) {
            atomicAdd(&den[(size_t)bz * denB + row0], rs0);
            atomicAdd(&den[(size_t)bz * denB + row1], rs1);
        }
    }
}

// ---------------- launch ----------------
extern "C" void kernel_launch(void* const* d_in, const int* in_sizes, int n_in,
                              void* d_out, int out_size)
{
    const float* x     = (const float*)d_in[0];
    const float* q_w   = (const float*)d_in[1];
    const float* q_b   = (const float*)d_in[2];
    const float* k_w   = (const float*)d_in[3];
    const float* k_b   = (const float*)d_in[4];
    const float* v_w   = (const float*)d_in[5];
    const float* v_b   = (const float*)d_in[6];
    const float* o_w   = (const float*)d_in[7];
    const float* o_b   = (const float*)d_in[8];
    const float* ln1_g = (const float*)d_in[9];
    const float* ln1_b = (const float*)d_in[10];
    const float* ln2_g = (const float*)d_in[11];
    const float* ln2_b = (const float*)d_in[12];
    const float* w1    = (const float*)d_in[13];
    const float* b1    = (const float*)d_in[14];
    const float* w2    = (const float*)d_in[15];
    const float* b2    = (const float*)d_in[16];
    float* out = (float*)d_out;

    __half *xn, *Qp, *Kp, *Vp, *Vt, *Pp, *attn, *xn2, *h;
    __half *qkvT, *oT, *w1T, *w2T;
    float *den, *x1;
    cudaGetSymbolAddress((void**)&xn,    g_xn);
    cudaGetSymbolAddress((void**)&Qp,    g_Q);
    cudaGetSymbolAddress((void**)&Kp,    g_K);
    cudaGetSymbolAddress((void**)&Vp,    g_V);
    cudaGetSymbolAddress((void**)&Vt,    g_Vt);
    cudaGetSymbolAddress((void**)&Pp,    g_P);
    cudaGetSymbolAddress((void**)&den,   g_den);
    cudaGetSymbolAddress((void**)&attn,  g_attn);
    cudaGetSymbolAddress((void**)&x1,    g_x1);
    cudaGetSymbolAddress((void**)&xn2,   g_xn2);
    cudaGetSymbolAddress((void**)&h,     g_h);
    cudaGetSymbolAddress((void**)&qkvT,  g_qkvT);
    cudaGetSymbolAddress((void**)&oT,    g_oT);
    cudaGetSymbolAddress((void**)&w1T,   g_w1T);
    cudaGetSymbolAddress((void**)&w2T,   g_w2T);

    cudaFuncSetAttribute(mm_kernel<EPI_QKV, 0, __half>,     cudaFuncAttributeMaxDynamicSharedMemorySize, MM_SMEM);
    cudaFuncSetAttribute(mm_kernel<EPI_SCORE, 1, __half>,   cudaFuncAttributeMaxDynamicSharedMemorySize, MM_SMEM);
    cudaFuncSetAttribute(mm_kernel<EPI_DIV, 2, __half>,     cudaFuncAttributeMaxDynamicSharedMemorySize, MM_SMEM);
    cudaFuncSetAttribute(mm_kernel<EPI_BIAS_RES, 0, float>, cudaFuncAttributeMaxDynamicSharedMemorySize, MM_SMEM);
    cudaFuncSetAttribute(mm_kernel<EPI_GELU, 0, __half>,    cudaFuncAttributeMaxDynamicSharedMemorySize, MM_SMEM);

    dim3 tb(32, 8);

    // LN1 -> fp16
    ln_kernel<<<Mq, 256>>>(x, ln1_g, ln1_b, xn);

    // weight transposes -> [N, K] K-major fp16
    tr_qkv_kernel<<<dim3(Eq/32, Dq/32, 3), tb>>>(q_w, k_w, v_w, qkvT);
    tr_kernel<float, __half><<<dim3(Dq/32, Eq/32, 1), tb>>>(o_w, oT, Eq, Dq, 0, 0);
    tr_kernel<float, __half><<<dim3(Fq/32, Dq/32, 1), tb>>>(w1, w1T, Dq, Fq, 0, 0);
    tr_kernel<float, __half><<<dim3(Dq/32, Fq/32, 1), tb>>>(w2, w2T, Fq, Dq, 0, 0);

    // Fused Q/K/V projection: B = qkvT [3E, D]
    mm_kernel<EPI_QKV, 0, __half><<<dim3(3*Eq/128, Mq/128, 1), 256, MM_SMEM>>>(
        xn, qkvT, Qp, Dq, Dq, Eq, Dq, 0, 0, 0, q_b, nullptr, 0, nullptr, 0,
        k_b, v_b, Kp, Vp);

    // V^T per batch: [Nq, Eq] -> [Eq, Nq]
    tr_kernel<__half, __half><<<dim3(Eq/32, Nq/32, Bq), tb>>>(Vp, Vt, Nq, Eq,
        (long long)Nq * Eq, (long long)Nq * Eq);

    // scores: P = tril(Q K^T); den = rowsum + 1e-6
    den_init<<<Mq/256, 256>>>(den);
    mm_kernel<EPI_SCORE, 1, __half><<<dim3(Nq/128, Nq/128, Bq), 256, MM_SMEM>>>(
        Qp, Kp, Pp, Eq, Eq, Nq, Eq,
        (long long)Nq * Eq, (long long)Nq * Eq, (long long)Nq * Nq,
        nullptr, nullptr, 0, den, Nq);

    // attn = (P @ V) / den  (B operand = V^T, K limited per tile row)
    mm_kernel<EPI_DIV, 2, __half><<<dim3(Eq/128, Nq/128, Bq), 256, MM_SMEM>>>(
        Pp, Vt, attn, Nq, Nq, Eq, Nq,
        (long long)Nq * Nq, (long long)Nq * Eq, (long long)Nq * Eq,
        nullptr, nullptr, 0, den, Nq);

    // output projection + residual (fp32 out)
    mm_kernel<EPI_BIAS_RES, 0, float><<<dim3(Dq/128, Mq/128, 1), 256, MM_SMEM>>>(
        attn, oT, x1, Eq, Eq, Dq, Eq, 0, 0, 0, o_b, x, 0, nullptr, 0);

    // LN2 + FFN
    ln_kernel<<<Mq, 256>>>(x1, ln2_g, ln2_b, xn2);
    mm_kernel<EPI_GELU, 0, __half><<<dim3(Fq/128, Mq/128, 1), 256, MM_SMEM>>>(
        xn2, w1T, h, Dq, Dq, Fq, Dq, 0, 0, 0, b1, nullptr, 0, nullptr, 0);
    mm_kernel<EPI_BIAS_RES, 0, float><<<dim3(Dq/128, Mq/128, 1), 256, MM_SMEM>>>(
        h, w2T, out, Fq, Fq, Dq, Fq, 0, 0, 0, b2, x1, 0, nullptr, 0);
}

// round 7
// speedup vs baseline: 1.6106x; 1.1472x over previous
#include <cuda_runtime.h>
#include <cuda_fp16.h>
#include <math.h>
#include <stdint.h>

// Problem shapes (fixed)
#define Bq 2
#define Nq 2048
#define Dq 1024
#define Eq 2048
#define Fq 4096
#define Mq (Bq*Nq)   // 4096 tokens

// ---------------- device scratch (no cudaMalloc allowed) ----------------
__device__ __align__(1024) __half g_xn   [(size_t)Mq*Dq];
__device__ __align__(1024) __half g_Q    [(size_t)Mq*Eq];
__device__ __align__(1024) __half g_K    [(size_t)Mq*Eq];
__device__ __align__(1024) __half g_V    [(size_t)Mq*Eq];
__device__ __align__(1024) __half g_Vt   [(size_t)Mq*Eq];
__device__ __align__(1024) __half g_P    [(size_t)Bq*Nq*Nq];
__device__ __align__(1024) float  g_den  [Mq];
__device__ __align__(1024) __half g_attn [(size_t)Mq*Eq];
__device__ __align__(1024) float  g_x1   [(size_t)Mq*Dq];
__device__ __align__(1024) __half g_xn2  [(size_t)Mq*Dq];
__device__ __align__(1024) __half g_h    [(size_t)Mq*Fq];
__device__ __align__(1024) __half g_qkvT [(size_t)3*Eq*Dq];
__device__ __align__(1024) __half g_oT   [(size_t)Dq*Eq];
__device__ __align__(1024) __half g_w1T  [(size_t)Dq*Fq];
__device__ __align__(1024) __half g_w2T  [(size_t)Dq*Fq];

// ---------------- helpers ----------------
__device__ __forceinline__ uint32_t smem_u32(const void* p) {
    uint32_t a;
    asm("{ .reg .u64 t; cvta.to.shared.u64 t, %1; cvt.u32.u64 %0, t; }" : "=r"(a) : "l"(p));
    return a;
}
__device__ __forceinline__ void cp16(uint32_t dst, const void* src) {
    asm volatile("cp.async.cg.shared.global [%0], [%1], 16;" :: "r"(dst), "l"(src) : "memory");
}
#define CP_COMMIT() asm volatile("cp.async.commit_group;" ::: "memory")
#define CP_WAIT1()  asm volatile("cp.async.wait_group 1;" ::: "memory")

__device__ __forceinline__ void ldsm4(uint32_t (&r)[4], uint32_t addr) {
    asm volatile("ldmatrix.sync.aligned.m8n8.x4.shared.b16 {%0,%1,%2,%3}, [%4];"
                 : "=r"(r[0]), "=r"(r[1]), "=r"(r[2]), "=r"(r[3]) : "r"(addr));
}
__device__ __forceinline__ void mma_f16(float (&c)[4], const uint32_t (&a)[4],
                                        uint32_t b0, uint32_t b1) {
    asm volatile("mma.sync.aligned.m16n8k16.row.col.f32.f16.f16.f32 "
                 "{%0,%1,%2,%3}, {%4,%5,%6,%7}, {%8,%9}, {%0,%1,%2,%3};"
                 : "+f"(c[0]), "+f"(c[1]), "+f"(c[2]), "+f"(c[3])
                 : "r"(a[0]), "r"(a[1]), "r"(a[2]), "r"(a[3]), "r"(b0), "r"(b1));
}
__device__ __forceinline__ void st2(float* p, float a, float b) {
    *reinterpret_cast<float2*>(p) = make_float2(a, b);
}
__device__ __forceinline__ void st2(__half* p, float a, float b) {
    *reinterpret_cast<__half2*>(p) = __floats2half2_rn(a, b);
}
__device__ __forceinline__ float ldf(const float* p)  { return *p; }
__device__ __forceinline__ float ldf(const __half* p) { return __half2float(*p); }

// ---------------- elementwise kernels ----------------
__global__ __launch_bounds__(256)
void ln_kernel(const float* __restrict__ x, const float* __restrict__ g,
               const float* __restrict__ b, __half* __restrict__ y)
{
    int row = blockIdx.x;
    int t = threadIdx.x;
    const float4* xr = reinterpret_cast<const float4*>(x + (size_t)row * Dq);
    float4 v = xr[t];
    float s  = v.x + v.y + v.z + v.w;
    float s2 = v.x*v.x + v.y*v.y + v.z*v.z + v.w*v.w;
    __shared__ float rs[8], rs2[8];
    #pragma unroll
    for (int o = 16; o > 0; o >>= 1) {
        s  += __shfl_down_sync(0xffffffffu, s,  o);
        s2 += __shfl_down_sync(0xffffffffu, s2, o);
    }
    if ((t & 31) == 0) { rs[t >> 5] = s; rs2[t >> 5] = s2; }
    __syncthreads();
    float ssum = 0.f, ssum2 = 0.f;
    #pragma unroll
    for (int i = 0; i < 8; i++) { ssum += rs[i]; ssum2 += rs2[i]; }
    float mu   = ssum * (1.0f / Dq);
    float var  = ssum2 * (1.0f / Dq) - mu * mu;
    float rstd = rsqrtf(var + 1e-5f);
    float4 gg = reinterpret_cast<const float4*>(g)[t];
    float4 bb = reinterpret_cast<const float4*>(b)[t];
    __half2 h01 = __floats2half2_rn((v.x - mu) * rstd * gg.x + bb.x,
                                    (v.y - mu) * rstd * gg.y + bb.y);
    __half2 h23 = __floats2half2_rn((v.z - mu) * rstd * gg.z + bb.z,
                                    (v.w - mu) * rstd * gg.w + bb.w);
    __half2* yp = reinterpret_cast<__half2*>(y + (size_t)row * Dq);
    yp[t * 2]     = h01;
    yp[t * 2 + 1] = h23;
}

__global__ void den_init(float* den) { den[blockIdx.x * 256 + threadIdx.x] = 1e-6f; }

// in [R,C] -> out [C,R], batched in z
template<typename Ti, typename To>
__global__ __launch_bounds__(256)
void tr_kernel(const Ti* __restrict__ in, To* __restrict__ out,
               int R, int C, long long sIn, long long sOut)
{
    __shared__ float t[32][33];
    const Ti* ib = in  + (size_t)blockIdx.z * sIn;
    To*       ob = out + (size_t)blockIdx.z * sOut;
    int c = blockIdx.x * 32 + threadIdx.x;
    int r = blockIdx.y * 32 + threadIdx.y;
    #pragma unroll
    for (int dy = 0; dy < 32; dy += 8)
        t[threadIdx.y + dy][threadIdx.x] = ldf(&ib[(size_t)(r + dy) * C + c]);
    __syncthreads();
    int c2 = blockIdx.y * 32 + threadIdx.x;
    int r2 = blockIdx.x * 32 + threadIdx.y;
    #pragma unroll
    for (int dy = 0; dy < 32; dy += 8)
        ob[(size_t)(r2 + dy) * R + c2] = (To)t[threadIdx.x][threadIdx.y + dy];
}

// three [Dq,Eq] fp32 sources -> one [3*Eq, Dq] fp16 dest (z picks source)
__global__ __launch_bounds__(256)
void tr_qkv_kernel(const float* __restrict__ s0, const float* __restrict__ s1,
                   const float* __restrict__ s2, __half* __restrict__ out)
{
    __shared__ float t[32][33];
    const float* ib = (blockIdx.z == 0) ? s0 : (blockIdx.z == 1) ? s1 : s2;
    __half* ob = out + (size_t)blockIdx.z * Eq * Dq;
    int c = blockIdx.x * 32 + threadIdx.x;
    int r = blockIdx.y * 32 + threadIdx.y;
    #pragma unroll
    for (int dy = 0; dy < 32; dy += 8)
        t[threadIdx.y + dy][threadIdx.x] = ib[(size_t)(r + dy) * Eq + c];
    __syncthreads();
    int c2 = blockIdx.y * 32 + threadIdx.x;
    int r2 = blockIdx.x * 32 + threadIdx.y;
    #pragma unroll
    for (int dy = 0; dy < 32; dy += 8)
        ob[(size_t)(r2 + dy) * Dq + c2] = (__half)t[threadIdx.x][threadIdx.y + dy];
}

// ---------------- fp16 mma.sync GEMM: 128x128 CTA, 8 warps (2Mx4N), warp 64x32 ----------------
// 3-stage cp.async pipeline (32KB/stage, 96KB), single barrier per k-chunk, 2 CTAs/SM.
__device__ __forceinline__ float gelu_exact(float v) {
    return 0.5f * v * (1.0f + erff(v * 0.70710678118654752f));
}
enum { EPI_BIAS = 0, EPI_FEAT = 1, EPI_GELU = 2, EPI_BIAS_RES = 3, EPI_DIV = 4, EPI_SCORE = 5, EPI_QKV = 6 };
// CM: 0 none, 1 score-causal, 2 PV (K limited to r0+128, heavy-first row order)

#define MM_SMEM (3 * 32768 + 1024)

template<int EPI, int CM, typename OutT>
__global__ __launch_bounds__(256, 2)
void mm_kernel(const __half* __restrict__ A, const __half* __restrict__ Bm, OutT* __restrict__ C,
               int ldA, int ldB, int ldC, int Kdim,
               long long sA, long long sB, long long sC,
               const float* __restrict__ bias,
               const float* __restrict__ res, long long sRes,
               float* __restrict__ den, int denB,
               const float* __restrict__ bias2 = nullptr,
               const float* __restrict__ bias3 = nullptr,
               OutT* __restrict__ C2 = nullptr,
               OutT* __restrict__ C3 = nullptr)
{
    int bz = blockIdx.z;
    int by = (CM == 2) ? ((int)gridDim.y - 1 - (int)blockIdx.y) : (int)blockIdx.y;  // heavy rows first for PV
    int r0 = by * 128, c0 = blockIdx.x * 128;
    if (CM == 1 && c0 > r0) return;
    const int keff = (CM == 2) ? (r0 + 128) : Kdim;
    const int nc = keff >> 6;                 // 64-half K chunks; nc >= 2 always

    const __half* Ab = A  + (size_t)bz * sA;
    const __half* Bb = Bm + (size_t)bz * sB;
    OutT*         Cb = C  + (size_t)bz * sC;

    extern __shared__ char dsm[];
    uint32_t s0 = (smem_u32(dsm) + 1023u) & ~1023u;   // stage s: A at s*32768, B at +16384

    int tid = threadIdx.x;

    // ---- loader: each thread does 4 A + 4 B cp.async of 16B per chunk ----
    int lm = tid >> 1;
    int cbase = (tid & 1) * 4;
    const __half* gA = Ab + (size_t)(r0 + lm) * ldA + cbase * 8;
    const __half* gB = Bb + (size_t)(c0 + lm) * ldB + cbase * 8;
    uint32_t sw[4];
    #pragma unroll
    for (int i = 0; i < 4; i++)
        sw[i] = (uint32_t)lm * 128u + (uint32_t)(((cbase + i) ^ (lm & 7)) << 4);

    // prologue: chunks 0,1 -> stages 0,1
    #pragma unroll
    for (int j = 0; j < 2; j++) {
        uint32_t aB = s0 + j * 32768, bB = aB + 16384;
        #pragma unroll
        for (int i = 0; i < 4; i++) {
            cp16(aB + sw[i], gA + j * 64 + i * 8);
            cp16(bB + sw[i], gB + j * 64 + i * 8);
        }
        CP_COMMIT();
    }

    // ---- fragment address bases ----
    int lane = tid & 31;
    int wm = (tid >> 5) & 1;
    int wn = tid >> 6;
    int aRow = wm * 64 + (lane & 15);
    int aHalf = lane >> 4;
    int bg = lane >> 3;
    int bRow = wn * 32 + ((bg >> 1) * 8) + (lane & 7);
    int bHalf = bg & 1;
    uint32_t aOff = (uint32_t)aRow * 128u;
    uint32_t bOff = (uint32_t)bRow * 128u;
    int aR7 = aRow & 7, bR7 = bRow & 7;

    float c[4][4][4];
    #pragma unroll
    for (int mt = 0; mt < 4; mt++)
        #pragma unroll
        for (int nt = 0; nt < 4; nt++)
            #pragma unroll
            for (int k = 0; k < 4; k++) c[mt][nt][k] = 0.f;

    // stage of chunk j = j % 3
    int s = 0;
    for (int i = 0; i < nc; i++) {
        CP_WAIT1();          // chunk i's group complete (chunk i+1 may still be in flight)
        __syncthreads();     // visibility + WAR: stage (i+2)%3 was consumed at iter i-1
        {
            int j = i + 2;
            if (j < nc) {
                int st = s + 2; if (st >= 3) st -= 3;
                uint32_t aB2 = s0 + st * 32768, bB2 = aB2 + 16384;
                #pragma unroll
                for (int ii = 0; ii < 4; ii++) {
                    cp16(aB2 + sw[ii], gA + (size_t)j * 64 + ii * 8);
                    cp16(bB2 + sw[ii], gB + (size_t)j * 64 + ii * 8);
                }
            }
            CP_COMMIT();
        }
        uint32_t aB = s0 + s * 32768, bB = aB + 16384;
        #pragma unroll
        for (int ks = 0; ks < 4; ks++) {
            uint32_t a[4][4];
            #pragma unroll
            for (int mt = 0; mt < 4; mt++) {
                uint32_t ad = aB + aOff + (uint32_t)(mt * 16 * 128)
                            + (uint32_t)(((ks * 2 + aHalf) ^ aR7) << 4);
                ldsm4(a[mt], ad);
            }
            uint32_t b[8];
            #pragma unroll
            for (int np = 0; np < 2; np++) {
                uint32_t bd = bB + bOff + (uint32_t)(np * 16 * 128)
                            + (uint32_t)(((ks * 2 + bHalf) ^ bR7) << 4);
                uint32_t r[4];
                ldsm4(r, bd);
                b[np*4+0]=r[0]; b[np*4+1]=r[1]; b[np*4+2]=r[2]; b[np*4+3]=r[3];
            }
            #pragma unroll
            for (int mt = 0; mt < 4; mt++) {
                mma_f16(c[mt][0], a[mt], b[0], b[1]);
                mma_f16(c[mt][1], a[mt], b[2], b[3]);
                mma_f16(c[mt][2], a[mt], b[4], b[5]);
                mma_f16(c[mt][3], a[mt], b[6], b[7]);
            }
        }
        if (++s >= 3) s = 0;
    }

    // ---- epilogue ----
    int seg = 0;
    const float* biasSel = bias;
    OutT* outSel = Cb;
    if (EPI == EPI_QKV) {
        seg = c0 >> 11;
        biasSel = (seg == 0) ? bias : (seg == 1) ? bias2 : bias3;
        outSel  = (seg == 0) ? C : (seg == 1) ? C2 : C3;
    }
    int cSub = (EPI == EPI_QKV) ? (c0 - (seg << 11)) : c0;

    int g4 = lane >> 2, q4 = lane & 3;
    #pragma unroll
    for (int mt = 0; mt < 4; mt++) {
        int row0 = r0 + wm * 64 + mt * 16 + g4;
        int row1 = row0 + 8;
        float d0 = 1.f, d1 = 1.f;
        if (EPI == EPI_DIV) {
            d0 = 1.0f / den[(size_t)bz * denB + row0];
            d1 = 1.0f / den[(size_t)bz * denB + row1];
        }
        float rs0 = 0.f, rs1 = 0.f;
        #pragma unroll
        for (int nt = 0; nt < 4; nt++) {
            int colL = cSub + wn * 32 + nt * 8 + q4 * 2;
            int col  = c0 + wn * 32 + nt * 8 + q4 * 2;
            float v0 = c[mt][nt][0], v1 = c[mt][nt][1];
            float v2 = c[mt][nt][2], v3 = c[mt][nt][3];
            if (EPI == EPI_BIAS || EPI == EPI_FEAT || EPI == EPI_GELU ||
                EPI == EPI_BIAS_RES || EPI == EPI_QKV) {
                float2 bv = *reinterpret_cast<const float2*>(biasSel + colL);
                v0 += bv.x; v1 += bv.y; v2 += bv.x; v3 += bv.y;
            }
            if (EPI == EPI_FEAT || (EPI == EPI_QKV && seg < 2)) {
                v0 = (v0 > 0.f) ? (v0 + 1.f) : expf(v0);
                v1 = (v1 > 0.f) ? (v1 + 1.f) : expf(v1);
                v2 = (v2 > 0.f) ? (v2 + 1.f) : expf(v2);
                v3 = (v3 > 0.f) ? (v3 + 1.f) : expf(v3);
            }
            if (EPI == EPI_GELU) {
                v0 = gelu_exact(v0); v1 = gelu_exact(v1);
                v2 = gelu_exact(v2); v3 = gelu_exact(v3);
            }
            if (EPI == EPI_BIAS_RES) {
                const float* rp0 = res + (size_t)bz * sRes + (size_t)row0 * ldC + colL;
                const float* rp1 = res + (size_t)bz * sRes + (size_t)row1 * ldC + colL;
                float2 r0v = *reinterpret_cast<const float2*>(rp0);
                float2 r1v = *reinterpret_cast<const float2*>(rp1);
                v0 += r0v.x; v1 += r0v.y; v2 += r1v.x; v3 += r1v.y;
            }
            if (EPI == EPI_DIV) {
                v0 *= d0; v1 *= d0; v2 *= d1; v3 *= d1;
            }
            if (EPI == EPI_SCORE) {
                if (col     > row0) v0 = 0.f;
                if (col + 1 > row0) v1 = 0.f;
                if (col     > row1) v2 = 0.f;
                if (col + 1 > row1) v3 = 0.f;
                rs0 += v0 + v1; rs1 += v2 + v3;
            }
            st2(outSel + (size_t)row0 * ldC + colL, v0, v1);
            st2(outSel + (size_t)row1 * ldC + colL, v2, v3);
        }
        if (EPI == EPI_SCORE) {
            atomicAdd(&den[(size_t)bz * denB + row0], rs0);
            atomicAdd(&den[(size_t)bz * denB + row1], rs1);
        }
    }
}

// ---------------- launch ----------------
extern "C" void kernel_launch(void* const* d_in, const int* in_sizes, int n_in,
                              void* d_out, int out_size)
{
    const float* x     = (const float*)d_in[0];
    const float* q_w   = (const float*)d_in[1];
    const float* q_b   = (const float*)d_in[2];
    const float* k_w   = (const float*)d_in[3];
    const float* k_b   = (const float*)d_in[4];
    const float* v_w   = (const float*)d_in[5];
    const float* v_b   = (const float*)d_in[6];
    const float* o_w   = (const float*)d_in[7];
    const float* o_b   = (const float*)d_in[8];
    const float* ln1_g = (const float*)d_in[9];
    const float* ln1_b = (const float*)d_in[10];
    const float* ln2_g = (const float*)d_in[11];
    const float* ln2_b = (const float*)d_in[12];
    const float* w1    = (const float*)d_in[13];
    const float* b1    = (const float*)d_in[14];
    const float* w2    = (const float*)d_in[15];
    const float* b2    = (const float*)d_in[16];
    float* out = (float*)d_out;

    __half *xn, *Qp, *Kp, *Vp, *Vt, *Pp, *attn, *xn2, *h;
    __half *qkvT, *oT, *w1T, *w2T;
    float *den, *x1;
    cudaGetSymbolAddress((void**)&xn,    g_xn);
    cudaGetSymbolAddress((void**)&Qp,    g_Q);
    cudaGetSymbolAddress((void**)&Kp,    g_K);
    cudaGetSymbolAddress((void**)&Vp,    g_V);
    cudaGetSymbolAddress((void**)&Vt,    g_Vt);
    cudaGetSymbolAddress((void**)&Pp,    g_P);
    cudaGetSymbolAddress((void**)&den,   g_den);
    cudaGetSymbolAddress((void**)&attn,  g_attn);
    cudaGetSymbolAddress((void**)&x1,    g_x1);
    cudaGetSymbolAddress((void**)&xn2,   g_xn2);
    cudaGetSymbolAddress((void**)&h,     g_h);
    cudaGetSymbolAddress((void**)&qkvT,  g_qkvT);
    cudaGetSymbolAddress((void**)&oT,    g_oT);
    cudaGetSymbolAddress((void**)&w1T,   g_w1T);
    cudaGetSymbolAddress((void**)&w2T,   g_w2T);

    cudaFuncSetAttribute(mm_kernel<EPI_QKV, 0, __half>,     cudaFuncAttributeMaxDynamicSharedMemorySize, MM_SMEM);
    cudaFuncSetAttribute(mm_kernel<EPI_SCORE, 1, __half>,   cudaFuncAttributeMaxDynamicSharedMemorySize, MM_SMEM);
    cudaFuncSetAttribute(mm_kernel<EPI_DIV, 2, __half>,     cudaFuncAttributeMaxDynamicSharedMemorySize, MM_SMEM);
    cudaFuncSetAttribute(mm_kernel<EPI_BIAS_RES, 0, float>, cudaFuncAttributeMaxDynamicSharedMemorySize, MM_SMEM);
    cudaFuncSetAttribute(mm_kernel<EPI_GELU, 0, __half>,    cudaFuncAttributeMaxDynamicSharedMemorySize, MM_SMEM);

    dim3 tb(32, 8);

    // LN1 -> fp16  (den_init has no deps; issue early)
    den_init<<<Mq/256, 256>>>(den);
    ln_kernel<<<Mq, 256>>>(x, ln1_g, ln1_b, xn);

    // weight transposes -> [N, K] K-major fp16
    tr_qkv_kernel<<<dim3(Eq/32, Dq/32, 3), tb>>>(q_w, k_w, v_w, qkvT);
    tr_kernel<float, __half><<<dim3(Dq/32, Eq/32, 1), tb>>>(o_w, oT, Eq, Dq, 0, 0);
    tr_kernel<float, __half><<<dim3(Fq/32, Dq/32, 1), tb>>>(w1, w1T, Dq, Fq, 0, 0);
    tr_kernel<float, __half><<<dim3(Dq/32, Fq/32, 1), tb>>>(w2, w2T, Fq, Dq, 0, 0);

    // Fused Q/K/V projection: B = qkvT [3E, D]
    mm_kernel<EPI_QKV, 0, __half><<<dim3(3*Eq/128, Mq/128, 1), 256, MM_SMEM>>>(
        xn, qkvT, Qp, Dq, Dq, Eq, Dq, 0, 0, 0, q_b, nullptr, 0, nullptr, 0,
        k_b, v_b, Kp, Vp);

    // V^T per batch: [Nq, Eq] -> [Eq, Nq]
    tr_kernel<__half, __half><<<dim3(Eq/32, Nq/32, Bq), tb>>>(Vp, Vt, Nq, Eq,
        (long long)Nq * Eq, (long long)Nq * Eq);

    // scores: P = tril(Q K^T); den = rowsum + 1e-6
    mm_kernel<EPI_SCORE, 1, __half><<<dim3(Nq/128, Nq/128, Bq), 256, MM_SMEM>>>(
        Qp, Kp, Pp, Eq, Eq, Nq, Eq,
        (long long)Nq * Eq, (long long)Nq * Eq, (long long)Nq * Nq,
        nullptr, nullptr, 0, den, Nq);

    // attn = (P @ V) / den  (B operand = V^T, K limited per tile row, heavy-first)
    mm_kernel<EPI_DIV, 2, __half><<<dim3(Eq/128, Nq/128, Bq), 256, MM_SMEM>>>(
        Pp, Vt, attn, Nq, Nq, Eq, Nq,
        (long long)Nq * Nq, (long long)Nq * Eq, (long long)Nq * Eq,
        nullptr, nullptr, 0, den, Nq);

    // output projection + residual (fp32 out)
    mm_kernel<EPI_BIAS_RES, 0, float><<<dim3(Dq/128, Mq/128, 1), 256, MM_SMEM>>>(
        attn, oT, x1, Eq, Eq, Dq, Eq, 0, 0, 0, o_b, x, 0, nullptr, 0);

    // LN2 + FFN
    ln_kernel<<<Mq, 256>>>(x1, ln2_g, ln2_b, xn2);
    mm_kernel<EPI_GELU, 0, __half><<<dim3(Fq/128, Mq/128, 1), 256, MM_SMEM>>>(
        xn2, w1T, h, Dq, Dq, Fq, Dq, 0, 0, 0, b1, nullptr, 0, nullptr, 0);
    mm_kernel<EPI_BIAS_RES, 0, float><<<dim3(Dq/128, Mq/128, 1), 256, MM_SMEM>>>(
        h, w2T, out, Fq, Fq, Dq, Fq, 0, 0, 0, b2, x1, 0, nullptr, 0);
}

// round 9
// speedup vs baseline: 1.6294x; 1.0116x over previous
#include <cuda_runtime.h>
#include <cuda_fp16.h>
#include <math.h>
#include <stdint.h>

// Problem shapes (fixed)
#define Bq 2
#define Nq 2048
#define Dq 1024
#define Eq 2048
#define Fq 4096
#define Mq (Bq*Nq)   // 4096 tokens

// ---------------- device scratch (no cudaMalloc allowed) ----------------
__device__ __align__(1024) __half g_xn   [(size_t)Mq*Dq];
__device__ __align__(1024) __half g_Q    [(size_t)Mq*Eq];
__device__ __align__(1024) __half g_K    [(size_t)Mq*Eq];
__device__ __align__(1024) __half g_Vt   [(size_t)Mq*Eq];
__device__ __align__(1024) __half g_P    [(size_t)Bq*Nq*Nq];
__device__ __align__(1024) float  g_den  [Mq];
__device__ __align__(1024) __half g_attn [(size_t)Mq*Eq];
__device__ __align__(1024) float  g_x1   [(size_t)Mq*Dq];
__device__ __align__(1024) __half g_xn2  [(size_t)Mq*Dq];
__device__ __align__(1024) __half g_h    [(size_t)Mq*Fq];
__device__ __align__(1024) __half g_qkvT [(size_t)3*Eq*Dq];
__device__ __align__(1024) __half g_oT   [(size_t)Dq*Eq];
__device__ __align__(1024) __half g_w1T  [(size_t)Dq*Fq];
__device__ __align__(1024) __half g_w2T  [(size_t)Dq*Fq];

// ---------------- helpers ----------------
__device__ __forceinline__ uint32_t smem_u32(const void* p) {
    uint32_t a;
    asm("{ .reg .u64 t; cvta.to.shared.u64 t, %1; cvt.u32.u64 %0, t; }" : "=r"(a) : "l"(p));
    return a;
}
__device__ __forceinline__ void cp16(uint32_t dst, const void* src) {
    asm volatile("cp.async.cg.shared.global [%0], [%1], 16;" :: "r"(dst), "l"(src) : "memory");
}
#define CP_COMMIT() asm volatile("cp.async.commit_group;" ::: "memory")
#define CP_WAIT1()  asm volatile("cp.async.wait_group 1;" ::: "memory")

__device__ __forceinline__ void ldsm4(uint32_t (&r)[4], uint32_t addr) {
    asm volatile("ldmatrix.sync.aligned.m8n8.x4.shared.b16 {%0,%1,%2,%3}, [%4];"
                 : "=r"(r[0]), "=r"(r[1]), "=r"(r[2]), "=r"(r[3]) : "r"(addr));
}
__device__ __forceinline__ void mma_f16(float (&c)[4], const uint32_t (&a)[4],
                                        uint32_t b0, uint32_t b1) {
    asm volatile("mma.sync.aligned.m16n8k16.row.col.f32.f16.f16.f32 "
                 "{%0,%1,%2,%3}, {%4,%5,%6,%7}, {%8,%9}, {%0,%1,%2,%3};"
                 : "+f"(c[0]), "+f"(c[1]), "+f"(c[2]), "+f"(c[3])
                 : "r"(a[0]), "r"(a[1]), "r"(a[2]), "r"(a[3]), "r"(b0), "r"(b1));
}
__device__ __forceinline__ void st2(float* p, float a, float b) {
    *reinterpret_cast<float2*>(p) = make_float2(a, b);
}
__device__ __forceinline__ void st2(__half* p, float a, float b) {
    *reinterpret_cast<__half2*>(p) = __floats2half2_rn(a, b);
}

// ---------------- elementwise kernels ----------------
__global__ __launch_bounds__(256)
void ln_kernel(const float* __restrict__ x, const float* __restrict__ g,
               const float* __restrict__ b, __half* __restrict__ y)
{
    int row = blockIdx.x;
    int t = threadIdx.x;
    const float4* xr = reinterpret_cast<const float4*>(x + (size_t)row * Dq);
    float4 v = xr[t];
    float s  = v.x + v.y + v.z + v.w;
    float s2 = v.x*v.x + v.y*v.y + v.z*v.z + v.w*v.w;
    __shared__ float rs[8], rs2[8];
    #pragma unroll
    for (int o = 16; o > 0; o >>= 1) {
        s  += __shfl_down_sync(0xffffffffu, s,  o);
        s2 += __shfl_down_sync(0xffffffffu, s2, o);
    }
    if ((t & 31) == 0) { rs[t >> 5] = s; rs2[t >> 5] = s2; }
    __syncthreads();
    float ssum = 0.f, ssum2 = 0.f;
    #pragma unroll
    for (int i = 0; i < 8; i++) { ssum += rs[i]; ssum2 += rs2[i]; }
    float mu   = ssum * (1.0f / Dq);
    float var  = ssum2 * (1.0f / Dq) - mu * mu;
    float rstd = rsqrtf(var + 1e-5f);
    float4 gg = reinterpret_cast<const float4*>(g)[t];
    float4 bb = reinterpret_cast<const float4*>(b)[t];
    __half2 h01 = __floats2half2_rn((v.x - mu) * rstd * gg.x + bb.x,
                                    (v.y - mu) * rstd * gg.y + bb.y);
    __half2 h23 = __floats2half2_rn((v.z - mu) * rstd * gg.z + bb.z,
                                    (v.w - mu) * rstd * gg.w + bb.w);
    __half2* yp = reinterpret_cast<__half2*>(y + (size_t)row * Dq);
    yp[t * 2]     = h01;
    yp[t * 2 + 1] = h23;
}

__global__ void den_init(float* den) { den[blockIdx.x * 256 + threadIdx.x] = 1e-6f; }

// all six weight transposes in ONE launch. 32x32 tiles, linearized block id.
__global__ __launch_bounds__(256)
void tr_all_kernel(const float* __restrict__ q_w, const float* __restrict__ k_w,
                   const float* __restrict__ v_w, const float* __restrict__ o_w,
                   const float* __restrict__ w1,  const float* __restrict__ w2,
                   __half* __restrict__ qkvT, __half* __restrict__ oT,
                   __half* __restrict__ w1T,  __half* __restrict__ w2T)
{
    __shared__ float t[32][33];
    int bid = blockIdx.x;
    const float* src; __half* dst; int R, C;
    if (bid < 6144) {
        int seg = bid >> 11; bid -= seg << 11;
        src = (seg == 0) ? q_w : (seg == 1) ? k_w : v_w;
        dst = qkvT + (size_t)seg * Eq * Dq;  R = Dq; C = Eq;
    } else if (bid < 8192)  { bid -= 6144;  src = o_w; dst = oT;  R = Eq; C = Dq; }
    else if (bid < 12288)   { bid -= 8192;  src = w1;  dst = w1T; R = Dq; C = Fq; }
    else                    { bid -= 12288; src = w2;  dst = w2T; R = Fq; C = Dq; }
    int tpr = C >> 5;
    int tx = bid % tpr, ty = bid / tpr;
    int c = tx * 32 + threadIdx.x;
    int r = ty * 32 + threadIdx.y;
    #pragma unroll
    for (int dy = 0; dy < 32; dy += 8)
        t[threadIdx.y + dy][threadIdx.x] = src[(size_t)(r + dy) * C + c];
    __syncthreads();
    int c2 = ty * 32 + threadIdx.x;
    int r2 = tx * 32 + threadIdx.y;
    #pragma unroll
    for (int dy = 0; dy < 32; dy += 8)
        dst[(size_t)(r2 + dy) * R + c2] = (__half)t[threadIdx.x][threadIdx.y + dy];
}

// ---------------- fp16 mma.sync GEMM: 128x128 CTA, 8 warps (2Mx4N), warp 64x32 ----------------
// 3-stage cp.async pipeline (32KB/stage, 96KB), single barrier per k-chunk, 2 CTAs/SM.
__device__ __forceinline__ float gelu_exact(float v) {
    return 0.5f * v * (1.0f + erff(v * 0.70710678118654752f));
}
enum { EPI_BIAS = 0, EPI_FEAT = 1, EPI_GELU = 2, EPI_BIAS_RES = 3, EPI_DIV = 4, EPI_SCORE = 5, EPI_QKV = 6 };
// CM: 0 none, 1 score-causal, 2 PV (K limited to r0+128, heavy-first row order)

#define MM_SMEM (3 * 32768 + 1024)
#define TSP 132   // padded stride for V-transpose staging

template<int EPI, int CM, typename OutT>
__global__ __launch_bounds__(256, 2)
void mm_kernel(const __half* __restrict__ A, const __half* __restrict__ Bm, OutT* __restrict__ C,
               int ldA, int ldB, int ldC, int Kdim,
               long long sA, long long sB, long long sC,
               const float* __restrict__ bias,
               const float* __restrict__ res, long long sRes,
               float* __restrict__ den, int denB,
               const float* __restrict__ bias2 = nullptr,
               const float* __restrict__ bias3 = nullptr,
               OutT* __restrict__ C2 = nullptr,
               OutT* __restrict__ C3 = nullptr)   // for EPI_QKV: C3 = Vt
{
    int bz = blockIdx.z;
    int by = (CM == 2) ? ((int)gridDim.y - 1 - (int)blockIdx.y) : (int)blockIdx.y;
    int r0 = by * 128, c0 = blockIdx.x * 128;
    if (CM == 1 && c0 > r0) return;
    const int keff = (CM == 2) ? (r0 + 128) : Kdim;
    const int nc = keff >> 6;

    const __half* Ab = A  + (size_t)bz * sA;
    const __half* Bb = Bm + (size_t)bz * sB;
    OutT*         Cb = C  + (size_t)bz * sC;

    extern __shared__ char dsm[];
    uint32_t s0 = (smem_u32(dsm) + 1023u) & ~1023u;

    int tid = threadIdx.x;

    int lm = tid >> 1;
    int cbase = (tid & 1) * 4;
    const __half* gA = Ab + (size_t)(r0 + lm) * ldA + cbase * 8;
    const __half* gB = Bb + (size_t)(c0 + lm) * ldB + cbase * 8;
    uint32_t sw[4];
    #pragma unroll
    for (int i = 0; i < 4; i++)
        sw[i] = (uint32_t)lm * 128u + (uint32_t)(((cbase + i) ^ (lm & 7)) << 4);

    #pragma unroll
    for (int j = 0; j < 2; j++) {
        uint32_t aB = s0 + j * 32768, bB = aB + 16384;
        #pragma unroll
        for (int i = 0; i < 4; i++) {
            cp16(aB + sw[i], gA + j * 64 + i * 8);
            cp16(bB + sw[i], gB + j * 64 + i * 8);
        }
        CP_COMMIT();
    }

    int lane = tid & 31;
    int wm = (tid >> 5) & 1;
    int wn = tid >> 6;
    int aRow = wm * 64 + (lane & 15);
    int aHalf = lane >> 4;
    int bg = lane >> 3;
    int bRow = wn * 32 + ((bg >> 1) * 8) + (lane & 7);
    int bHalf = bg & 1;
    uint32_t aOff = (uint32_t)aRow * 128u;
    uint32_t bOff = (uint32_t)bRow * 128u;
    int aR7 = aRow & 7, bR7 = bRow & 7;

    float c[4][4][4];
    #pragma unroll
    for (int mt = 0; mt < 4; mt++)
        #pragma unroll
        for (int nt = 0; nt < 4; nt++)
            #pragma unroll
            for (int k = 0; k < 4; k++) c[mt][nt][k] = 0.f;

    int s = 0;
    for (int i = 0; i < nc; i++) {
        CP_WAIT1();
        __syncthreads();
        {
            int j = i + 2;
            if (j < nc) {
                int st = s + 2; if (st >= 3) st -= 3;
                uint32_t aB2 = s0 + st * 32768, bB2 = aB2 + 16384;
                #pragma unroll
                for (int ii = 0; ii < 4; ii++) {
                    cp16(aB2 + sw[ii], gA + (size_t)j * 64 + ii * 8);
                    cp16(bB2 + sw[ii], gB + (size_t)j * 64 + ii * 8);
                }
            }
            CP_COMMIT();
        }
        uint32_t aB = s0 + s * 32768, bB = aB + 16384;
        #pragma unroll
        for (int ks = 0; ks < 4; ks++) {
            uint32_t a[4][4];
            #pragma unroll
            for (int mt = 0; mt < 4; mt++) {
                uint32_t ad = aB + aOff + (uint32_t)(mt * 16 * 128)
                            + (uint32_t)(((ks * 2 + aHalf) ^ aR7) << 4);
                ldsm4(a[mt], ad);
            }
            uint32_t b[8];
            #pragma unroll
            for (int np = 0; np < 2; np++) {
                uint32_t bd = bB + bOff + (uint32_t)(np * 16 * 128)
                            + (uint32_t)(((ks * 2 + bHalf) ^ bR7) << 4);
                uint32_t r[4];
                ldsm4(r, bd);
                b[np*4+0]=r[0]; b[np*4+1]=r[1]; b[np*4+2]=r[2]; b[np*4+3]=r[3];
            }
            #pragma unroll
            for (int mt = 0; mt < 4; mt++) {
                mma_f16(c[mt][0], a[mt], b[0], b[1]);
                mma_f16(c[mt][1], a[mt], b[2], b[3]);
                mma_f16(c[mt][2], a[mt], b[4], b[5]);
                mma_f16(c[mt][3], a[mt], b[6], b[7]);
            }
        }
        if (++s >= 3) s = 0;
    }

    // ---- epilogue ----
    int seg = 0;
    const float* biasSel = bias;
    OutT* outSel = Cb;
    if (EPI == EPI_QKV) {
        seg = c0 >> 11;                       // 0:Q 1:K 2:V(->Vt)
        biasSel = (seg == 0) ? bias : (seg == 1) ? bias2 : bias3;
        outSel  = (seg == 0) ? C : (seg == 1) ? C2 : C;   // seg2 handled via smem path
    }
    int cSub = (EPI == EPI_QKV) ? (c0 - (seg << 11)) : c0;

    bool vpath = (EPI == EPI_QKV) && (seg == 2);
    __half* ts = reinterpret_cast<__half*>(dsm);
    if (vpath) __syncthreads();   // mainloop smem reads done before reuse (uniform per CTA)

    int g4 = lane >> 2, q4 = lane & 3;
    #pragma unroll
    for (int mt = 0; mt < 4; mt++) {
        int rl0 = wm * 64 + mt * 16 + g4;     // local row
        int row0 = r0 + rl0;
        int row1 = row0 + 8;
        float d0 = 1.f, d1 = 1.f;
        if (EPI == EPI_DIV) {
            d0 = 1.0f / den[(size_t)bz * denB + row0];
            d1 = 1.0f / den[(size_t)bz * denB + row1];
        }
        float rs0 = 0.f, rs1 = 0.f;
        #pragma unroll
        for (int nt = 0; nt < 4; nt++) {
            int lc   = wn * 32 + nt * 8 + q4 * 2;          // local col
            int colL = cSub + lc;
            int col  = c0 + lc;
            float v0 = c[mt][nt][0], v1 = c[mt][nt][1];
            float v2 = c[mt][nt][2], v3 = c[mt][nt][3];
            if (EPI == EPI_BIAS || EPI == EPI_FEAT || EPI == EPI_GELU ||
                EPI == EPI_BIAS_RES || EPI == EPI_QKV) {
                float2 bv = *reinterpret_cast<const float2*>(biasSel + colL);
                v0 += bv.x; v1 += bv.y; v2 += bv.x; v3 += bv.y;
            }
            if (EPI == EPI_FEAT || (EPI == EPI_QKV && seg < 2)) {
                v0 = (v0 > 0.f) ? (v0 + 1.f) : expf(v0);
                v1 = (v1 > 0.f) ? (v1 + 1.f) : expf(v1);
                v2 = (v2 > 0.f) ? (v2 + 1.f) : expf(v2);
                v3 = (v3 > 0.f) ? (v3 + 1.f) : expf(v3);
            }
            if (EPI == EPI_GELU) {
                v0 = gelu_exact(v0); v1 = gelu_exact(v1);
                v2 = gelu_exact(v2); v3 = gelu_exact(v3);
            }
            if (EPI == EPI_BIAS_RES) {
                const float* rp0 = res + (size_t)bz * sRes + (size_t)row0 * ldC + colL;
                const float* rp1 = res + (size_t)bz * sRes + (size_t)row1 * ldC + colL;
                float2 r0v = *reinterpret_cast<const float2*>(rp0);
                float2 r1v = *reinterpret_cast<const float2*>(rp1);
                v0 += r0v.x; v1 += r0v.y; v2 += r1v.x; v3 += r1v.y;
            }
            if (EPI == EPI_DIV) {
                v0 *= d0; v1 *= d0; v2 *= d1; v3 *= d1;
            }
            if (EPI == EPI_SCORE) {
                if (col     > row0) v0 = 0.f;
                if (col + 1 > row0) v1 = 0.f;
                if (col     > row1) v2 = 0.f;
                if (col + 1 > row1) v3 = 0.f;
                rs0 += v0 + v1; rs1 += v2 + v3;
            }
            if (vpath) {
                *reinterpret_cast<__half2*>(ts + rl0 * TSP + lc)       = __floats2half2_rn(v0, v1);
                *reinterpret_cast<__half2*>(ts + (rl0 + 8) * TSP + lc) = __floats2half2_rn(v2, v3);
            } else {
                st2(outSel + (size_t)row0 * ldC + colL, v0, v1);
                st2(outSel + (size_t)row1 * ldC + colL, v2, v3);
            }
        }
        if (EPI == EPI_SCORE) {
            atomicAdd(&den[(size_t)bz * denB + row0], rs0);
            atomicAdd(&den[(size_t)bz * denB + row1], rs1);
        }
    }

    if constexpr (EPI == EPI_QKV) {
        if (vpath) {
            __syncthreads();
            // write transposed tile: Vt[e][seq], coalesced 16B per thread-chunk
            int cc = tid & 127, hh = tid >> 7;     // column 0..127, half 0/1
            size_t b = (size_t)(r0 >> 11);
            int seqBase = r0 & 2047;
            __half* dst = C3 + b * (size_t)(Nq * Eq) + (size_t)(cSub + cc) * Nq + seqBase + hh * 64;
            #pragma unroll
            for (int i0 = 0; i0 < 64; i0 += 8) {
                __half tmp[8];
                #pragma unroll
                for (int k = 0; k < 8; k++)
                    tmp[k] = ts[(hh * 64 + i0 + k) * TSP + cc];
                *reinterpret_cast<uint4*>(dst + i0) = *reinterpret_cast<const uint4*>(tmp);
            }
        }
    }
}

// ---------------- launch ----------------
extern "C" void kernel_launch(void* const* d_in, const int* in_sizes, int n_in,
                              void* d_out, int out_size)
{
    const float* x     = (const float*)d_in[0];
    const float* q_w   = (const float*)d_in[1];
    const float* q_b   = (const float*)d_in[2];
    const float* k_w   = (const float*)d_in[3];
    const float* k_b   = (const float*)d_in[4];
    const float* v_w   = (const float*)d_in[5];
    const float* v_b   = (const float*)d_in[6];
    const float* o_w   = (const float*)d_in[7];
    const float* o_b   = (const float*)d_in[8];
    const float* ln1_g = (const float*)d_in[9];
    const float* ln1_b = (const float*)d_in[10];
    const float* ln2_g = (const float*)d_in[11];
    const float* ln2_b = (const float*)d_in[12];
    const float* w1    = (const float*)d_in[13];
    const float* b1    = (const float*)d_in[14];
    const float* w2    = (const float*)d_in[15];
    const float* b2    = (const float*)d_in[16];
    float* out = (float*)d_out;

    __half *xn, *Qp, *Kp, *Vt, *Pp, *attn, *xn2, *h;
    __half *qkvT, *oT, *w1T, *w2T;
    float *den, *x1;
    cudaGetSymbolAddress((void**)&xn,    g_xn);
    cudaGetSymbolAddress((void**)&Qp,    g_Q);
    cudaGetSymbolAddress((void**)&Kp,    g_K);
    cudaGetSymbolAddress((void**)&Vt,    g_Vt);
    cudaGetSymbolAddress((void**)&Pp,    g_P);
    cudaGetSymbolAddress((void**)&den,   g_den);
    cudaGetSymbolAddress((void**)&attn,  g_attn);
    cudaGetSymbolAddress((void**)&x1,    g_x1);
    cudaGetSymbolAddress((void**)&xn2,   g_xn2);
    cudaGetSymbolAddress((void**)&h,     g_h);
    cudaGetSymbolAddress((void**)&qkvT,  g_qkvT);
    cudaGetSymbolAddress((void**)&oT,    g_oT);
    cudaGetSymbolAddress((void**)&w1T,   g_w1T);
    cudaGetSymbolAddress((void**)&w2T,   g_w2T);

    cudaFuncSetAttribute(mm_kernel<EPI_QKV, 0, __half>,     cudaFuncAttributeMaxDynamicSharedMemorySize, MM_SMEM);
    cudaFuncSetAttribute(mm_kernel<EPI_SCORE, 1, __half>,   cudaFuncAttributeMaxDynamicSharedMemorySize, MM_SMEM);
    cudaFuncSetAttribute(mm_kernel<EPI_DIV, 2, __half>,     cudaFuncAttributeMaxDynamicSharedMemorySize, MM_SMEM);
    cudaFuncSetAttribute(mm_kernel<EPI_BIAS_RES, 0, float>, cudaFuncAttributeMaxDynamicSharedMemorySize, MM_SMEM);
    cudaFuncSetAttribute(mm_kernel<EPI_GELU, 0, __half>,    cudaFuncAttributeMaxDynamicSharedMemorySize, MM_SMEM);

    // den init + LN1 + all weight transposes (one launch)
    den_init<<<Mq/256, 256>>>(den);
    ln_kernel<<<Mq, 256>>>(x, ln1_g, ln1_b, xn);
    tr_all_kernel<<<16384, dim3(32, 8)>>>(q_w, k_w, v_w, o_w, w1, w2, qkvT, oT, w1T, w2T);

    // Fused Q/K/V projection; V written transposed to Vt in-epilogue
    mm_kernel<EPI_QKV, 0, __half><<<dim3(3*Eq/128, Mq/128, 1), 256, MM_SMEM>>>(
        xn, qkvT, Qp, Dq, Dq, Eq, Dq, 0, 0, 0, q_b, nullptr, 0, nullptr, 0,
        k_b, v_b, Kp, Vt);

    // scores: P = tril(Q K^T); den = rowsum + 1e-6
    mm_kernel<EPI_SCORE, 1, __half><<<dim3(Nq/128, Nq/128, Bq), 256, MM_SMEM>>>(
        Qp, Kp, Pp, Eq, Eq, Nq, Eq,
        (long long)Nq * Eq, (long long)Nq * Eq, (long long)Nq * Nq,
        nullptr, nullptr, 0, den, Nq);

    // attn = (P @ V) / den  (B operand = V^T, K limited per tile row, heavy-first)
    mm_kernel<EPI_DIV, 2, __half><<<dim3(Eq/128, Nq/128, Bq), 256, MM_SMEM>>>(
        Pp, Vt, attn, Nq, Nq, Eq, Nq,
        (long long)Nq * Nq, (long long)Nq * Eq, (long long)Nq * Eq,
        nullptr, nullptr, 0, den, Nq);

    // output projection + residual (fp32 out)
    mm_kernel<EPI_BIAS_RES, 0, float><<<dim3(Dq/128, Mq/128, 1), 256, MM_SMEM>>>(
        attn, oT, x1, Eq, Eq, Dq, Eq, 0, 0, 0, o_b, x, 0, nullptr, 0);

    // LN2 + FFN
    ln_kernel<<<Mq, 256>>>(x1, ln2_g, ln2_b, xn2);
    mm_kernel<EPI_GELU, 0, __half><<<dim3(Fq/128, Mq/128, 1), 256, MM_SMEM>>>(
        xn2, w1T, h, Dq, Dq, Fq, Dq, 0, 0, 0, b1, nullptr, 0, nullptr, 0);
    mm_kernel<EPI_BIAS_RES, 0, float><<<dim3(Dq/128, Mq/128, 1), 256, MM_SMEM>>>(
        h, w2T, out, Fq, Fq, Dq, Fq, 0, 0, 0, b2, x1, 0, nullptr, 0);
}

// round 10
// speedup vs baseline: 1.6432x; 1.0085x over previous
#include <cuda_runtime.h>
#include <cuda_fp16.h>
#include <math.h>
#include <stdint.h>

// Problem shapes (fixed)
#define Bq 2
#define Nq 2048
#define Dq 1024
#define Eq 2048
#define Fq 4096
#define Mq (Bq*Nq)   // 4096 tokens

// ---------------- device scratch (no cudaMalloc allowed) ----------------
__device__ __align__(1024) __half g_xn   [(size_t)Mq*Dq];
__device__ __align__(1024) __half g_Q    [(size_t)Mq*Eq];
__device__ __align__(1024) __half g_K    [(size_t)Mq*Eq];
__device__ __align__(1024) __half g_Vt   [(size_t)Mq*Eq];
__device__ __align__(1024) __half g_P    [(size_t)Bq*Nq*Nq];
__device__ __align__(1024) float  g_den  [Mq];
__device__ __align__(1024) float  g_s1   [Mq];
__device__ __align__(1024) float  g_s2   [Mq];
__device__ __align__(1024) __half g_attn [(size_t)Mq*Eq];
__device__ __align__(1024) float  g_x1   [(size_t)Mq*Dq];
__device__ __align__(1024) __half g_xn2  [(size_t)Mq*Dq];
__device__ __align__(1024) __half g_h    [(size_t)Mq*Fq];
__device__ __align__(1024) __half g_qkvT [(size_t)3*Eq*Dq];
__device__ __align__(1024) __half g_oT   [(size_t)Dq*Eq];
__device__ __align__(1024) __half g_w1T  [(size_t)Dq*Fq];
__device__ __align__(1024) __half g_w2T  [(size_t)Dq*Fq];

// ---------------- helpers ----------------
__device__ __forceinline__ uint32_t smem_u32(const void* p) {
    uint32_t a;
    asm("{ .reg .u64 t; cvta.to.shared.u64 t, %1; cvt.u32.u64 %0, t; }" : "=r"(a) : "l"(p));
    return a;
}
__device__ __forceinline__ void cp16(uint32_t dst, const void* src) {
    asm volatile("cp.async.cg.shared.global [%0], [%1], 16;" :: "r"(dst), "l"(src) : "memory");
}
#define CP_COMMIT() asm volatile("cp.async.commit_group;" ::: "memory")
#define CP_WAIT1()  asm volatile("cp.async.wait_group 1;" ::: "memory")

__device__ __forceinline__ void ldsm4(uint32_t (&r)[4], uint32_t addr) {
    asm volatile("ldmatrix.sync.aligned.m8n8.x4.shared.b16 {%0,%1,%2,%3}, [%4];"
                 : "=r"(r[0]), "=r"(r[1]), "=r"(r[2]), "=r"(r[3]) : "r"(addr));
}
__device__ __forceinline__ void mma_f16(float (&c)[4], const uint32_t (&a)[4],
                                        uint32_t b0, uint32_t b1) {
    asm volatile("mma.sync.aligned.m16n8k16.row.col.f32.f16.f16.f32 "
                 "{%0,%1,%2,%3}, {%4,%5,%6,%7}, {%8,%9}, {%0,%1,%2,%3};"
                 : "+f"(c[0]), "+f"(c[1]), "+f"(c[2]), "+f"(c[3])
                 : "r"(a[0]), "r"(a[1]), "r"(a[2]), "r"(a[3]), "r"(b0), "r"(b1));
}
__device__ __forceinline__ void st2(float* p, float a, float b) {
    *reinterpret_cast<float2*>(p) = make_float2(a, b);
}
__device__ __forceinline__ void st2(__half* p, float a, float b) {
    *reinterpret_cast<__half2*>(p) = __floats2half2_rn(a, b);
}

// ---------------- prep: weight transposes + den/stat init + LN1, one launch ----------------
// blocks [0,16384): transposes; [16384,16400): init; [16400,20496): LN1 rows
__global__ __launch_bounds__(256)
void prep_kernel(const float* __restrict__ x, const float* __restrict__ ln1_g,
                 const float* __restrict__ ln1_b, __half* __restrict__ xn,
                 float* __restrict__ den, float* __restrict__ s1, float* __restrict__ s2,
                 const float* __restrict__ q_w, const float* __restrict__ k_w,
                 const float* __restrict__ v_w, const float* __restrict__ o_w,
                 const float* __restrict__ w1,  const float* __restrict__ w2,
                 __half* __restrict__ qkvT, __half* __restrict__ oT,
                 __half* __restrict__ w1T,  __half* __restrict__ w2T)
{
    int bid = blockIdx.x;
    if (bid < 16384) {
        __shared__ float t[32][33];
        const float* src; __half* dst; int R, C;
        if (bid < 6144) {
            int seg = bid >> 11; bid -= seg << 11;
            src = (seg == 0) ? q_w : (seg == 1) ? k_w : v_w;
            dst = qkvT + (size_t)seg * Eq * Dq;  R = Dq; C = Eq;
        } else if (bid < 8192)  { bid -= 6144;  src = o_w; dst = oT;  R = Eq; C = Dq; }
        else if (bid < 12288)   { bid -= 8192;  src = w1;  dst = w1T; R = Dq; C = Fq; }
        else                    { bid -= 12288; src = w2;  dst = w2T; R = Fq; C = Dq; }
        int tpr = C >> 5;
        int tx = bid % tpr, ty = bid / tpr;
        int c = tx * 32 + threadIdx.x;
        int r = ty * 32 + threadIdx.y;
        #pragma unroll
        for (int dy = 0; dy < 32; dy += 8)
            t[threadIdx.y + dy][threadIdx.x] = src[(size_t)(r + dy) * C + c];
        __syncthreads();
        int c2 = ty * 32 + threadIdx.x;
        int r2 = tx * 32 + threadIdx.y;
        #pragma unroll
        for (int dy = 0; dy < 32; dy += 8)
            dst[(size_t)(r2 + dy) * R + c2] = (__half)t[threadIdx.x][threadIdx.y + dy];
    } else if (bid < 16400) {
        int idx = (bid - 16384) * 256 + threadIdx.y * 32 + threadIdx.x;
        den[idx] = 1e-6f; s1[idx] = 0.f; s2[idx] = 0.f;
    } else {
        int row = bid - 16400;
        int t = threadIdx.y * 32 + threadIdx.x;
        const float4* xr = reinterpret_cast<const float4*>(x + (size_t)row * Dq);
        float4 v = xr[t];
        float s  = v.x + v.y + v.z + v.w;
        float s2r = v.x*v.x + v.y*v.y + v.z*v.z + v.w*v.w;
        __shared__ float rs[8], rs2[8];
        #pragma unroll
        for (int o = 16; o > 0; o >>= 1) {
            s   += __shfl_down_sync(0xffffffffu, s,   o);
            s2r += __shfl_down_sync(0xffffffffu, s2r, o);
        }
        if ((t & 31) == 0) { rs[t >> 5] = s; rs2[t >> 5] = s2r; }
        __syncthreads();
        float ssum = 0.f, ssum2 = 0.f;
        #pragma unroll
        for (int i = 0; i < 8; i++) { ssum += rs[i]; ssum2 += rs2[i]; }
        float mu   = ssum * (1.0f / Dq);
        float var  = ssum2 * (1.0f / Dq) - mu * mu;
        float rstd = rsqrtf(var + 1e-5f);
        float4 gg = reinterpret_cast<const float4*>(ln1_g)[t];
        float4 bb = reinterpret_cast<const float4*>(ln1_b)[t];
        __half2 h01 = __floats2half2_rn((v.x - mu) * rstd * gg.x + bb.x,
                                        (v.y - mu) * rstd * gg.y + bb.y);
        __half2 h23 = __floats2half2_rn((v.z - mu) * rstd * gg.z + bb.z,
                                        (v.w - mu) * rstd * gg.w + bb.w);
        __half2* yp = reinterpret_cast<__half2*>(xn + (size_t)row * Dq);
        yp[t * 2]     = h01;
        yp[t * 2 + 1] = h23;
    }
}

// LN2 with precomputed stats (no reduction)
__global__ __launch_bounds__(256)
void ln2s_kernel(const float* __restrict__ x, const float* __restrict__ s1,
                 const float* __restrict__ s2, const float* __restrict__ g,
                 const float* __restrict__ b, __half* __restrict__ y)
{
    int row = blockIdx.x;
    int t = threadIdx.x;
    float mu   = s1[row] * (1.0f / Dq);
    float var  = s2[row] * (1.0f / Dq) - mu * mu;
    float rstd = rsqrtf(var + 1e-5f);
    float4 v = reinterpret_cast<const float4*>(x + (size_t)row * Dq)[t];
    float4 gg = reinterpret_cast<const float4*>(g)[t];
    float4 bb = reinterpret_cast<const float4*>(b)[t];
    __half2 h01 = __floats2half2_rn((v.x - mu) * rstd * gg.x + bb.x,
                                    (v.y - mu) * rstd * gg.y + bb.y);
    __half2 h23 = __floats2half2_rn((v.z - mu) * rstd * gg.z + bb.z,
                                    (v.w - mu) * rstd * gg.w + bb.w);
    __half2* yp = reinterpret_cast<__half2*>(y + (size_t)row * Dq);
    yp[t * 2]     = h01;
    yp[t * 2 + 1] = h23;
}

// ---------------- fp16 mma.sync GEMM: 128x128 CTA, 8 warps (2Mx4N), warp 64x32 ----------------
// 3-stage cp.async pipeline (32KB/stage, 96KB), single barrier per k-chunk, 2 CTAs/SM.
__device__ __forceinline__ float gelu_exact(float v) {
    return 0.5f * v * (1.0f + erff(v * 0.70710678118654752f));
}
enum { EPI_BIAS = 0, EPI_FEAT = 1, EPI_GELU = 2, EPI_BIAS_RES = 3, EPI_DIV = 4, EPI_SCORE = 5, EPI_QKV = 6, EPI_OPROJ = 7 };
// CM: 0 none, 1 score-causal, 2 PV (K limited to r0+128, heavy-first row order)

#define MM_SMEM (3 * 32768 + 1024)
#define TSP 132   // padded stride for V-transpose staging

template<int EPI, int CM, typename OutT>
__global__ __launch_bounds__(256, 2)
void mm_kernel(const __half* __restrict__ A, const __half* __restrict__ Bm, OutT* __restrict__ C,
               int ldA, int ldB, int ldC, int Kdim,
               long long sA, long long sB, long long sC,
               const float* __restrict__ bias,
               const float* __restrict__ res, long long sRes,
               float* __restrict__ den, int denB,
               const float* __restrict__ bias2 = nullptr,
               const float* __restrict__ bias3 = nullptr,
               OutT* __restrict__ C2 = nullptr,    // EPI_QKV: K out; EPI_OPROJ: s1
               OutT* __restrict__ C3 = nullptr)    // EPI_QKV: Vt;   EPI_OPROJ: s2
{
    int bz = blockIdx.z;
    int by = (CM == 2) ? ((int)gridDim.y - 1 - (int)blockIdx.y) : (int)blockIdx.y;
    int r0 = by * 128, c0 = blockIdx.x * 128;
    if (CM == 1 && c0 > r0) return;
    const int keff = (CM == 2) ? (r0 + 128) : Kdim;
    const int nc = keff >> 6;

    const __half* Ab = A  + (size_t)bz * sA;
    const __half* Bb = Bm + (size_t)bz * sB;
    OutT*         Cb = C  + (size_t)bz * sC;

    extern __shared__ char dsm[];
    uint32_t s0 = (smem_u32(dsm) + 1023u) & ~1023u;

    int tid = threadIdx.x;

    int lm = tid >> 1;
    int cbase = (tid & 1) * 4;
    const __half* gA = Ab + (size_t)(r0 + lm) * ldA + cbase * 8;
    const __half* gB = Bb + (size_t)(c0 + lm) * ldB + cbase * 8;
    uint32_t sw[4];
    #pragma unroll
    for (int i = 0; i < 4; i++)
        sw[i] = (uint32_t)lm * 128u + (uint32_t)(((cbase + i) ^ (lm & 7)) << 4);

    #pragma unroll
    for (int j = 0; j < 2; j++) {
        uint32_t aB = s0 + j * 32768, bB = aB + 16384;
        #pragma unroll
        for (int i = 0; i < 4; i++) {
            cp16(aB + sw[i], gA + j * 64 + i * 8);
            cp16(bB + sw[i], gB + j * 64 + i * 8);
        }
        CP_COMMIT();
    }

    int lane = tid & 31;
    int wm = (tid >> 5) & 1;
    int wn = tid >> 6;
    int aRow = wm * 64 + (lane & 15);
    int aHalf = lane >> 4;
    int bg = lane >> 3;
    int bRow = wn * 32 + ((bg >> 1) * 8) + (lane & 7);
    int bHalf = bg & 1;
    uint32_t aOff = (uint32_t)aRow * 128u;
    uint32_t bOff = (uint32_t)bRow * 128u;
    int aR7 = aRow & 7, bR7 = bRow & 7;

    float c[4][4][4];
    #pragma unroll
    for (int mt = 0; mt < 4; mt++)
        #pragma unroll
        for (int nt = 0; nt < 4; nt++)
            #pragma unroll
            for (int k = 0; k < 4; k++) c[mt][nt][k] = 0.f;

    int s = 0;
    for (int i = 0; i < nc; i++) {
        CP_WAIT1();
        __syncthreads();
        {
            int j = i + 2;
            if (j < nc) {
                int st = s + 2; if (st >= 3) st -= 3;
                uint32_t aB2 = s0 + st * 32768, bB2 = aB2 + 16384;
                #pragma unroll
                for (int ii = 0; ii < 4; ii++) {
                    cp16(aB2 + sw[ii], gA + (size_t)j * 64 + ii * 8);
                    cp16(bB2 + sw[ii], gB + (size_t)j * 64 + ii * 8);
                }
            }
            CP_COMMIT();
        }
        uint32_t aB = s0 + s * 32768, bB = aB + 16384;
        #pragma unroll
        for (int ks = 0; ks < 4; ks++) {
            uint32_t a[4][4];
            #pragma unroll
            for (int mt = 0; mt < 4; mt++) {
                uint32_t ad = aB + aOff + (uint32_t)(mt * 16 * 128)
                            + (uint32_t)(((ks * 2 + aHalf) ^ aR7) << 4);
                ldsm4(a[mt], ad);
            }
            uint32_t b[8];
            #pragma unroll
            for (int np = 0; np < 2; np++) {
                uint32_t bd = bB + bOff + (uint32_t)(np * 16 * 128)
                            + (uint32_t)(((ks * 2 + bHalf) ^ bR7) << 4);
                uint32_t r[4];
                ldsm4(r, bd);
                b[np*4+0]=r[0]; b[np*4+1]=r[1]; b[np*4+2]=r[2]; b[np*4+3]=r[3];
            }
            #pragma unroll
            for (int mt = 0; mt < 4; mt++) {
                mma_f16(c[mt][0], a[mt], b[0], b[1]);
                mma_f16(c[mt][1], a[mt], b[2], b[3]);
                mma_f16(c[mt][2], a[mt], b[4], b[5]);
                mma_f16(c[mt][3], a[mt], b[6], b[7]);
            }
        }
        if (++s >= 3) s = 0;
    }

    // ---- epilogue ----
    int seg = 0;
    const float* biasSel = bias;
    OutT* outSel = Cb;
    if (EPI == EPI_QKV) {
        seg = c0 >> 11;                       // 0:Q 1:K 2:V(->Vt)
        biasSel = (seg == 0) ? bias : (seg == 1) ? bias2 : bias3;
        outSel  = (seg == 0) ? C : (seg == 1) ? C2 : C;
    }
    int cSub = (EPI == EPI_QKV) ? (c0 - (seg << 11)) : c0;

    bool vpath = (EPI == EPI_QKV) && (seg == 2);
    __half* ts = reinterpret_cast<__half*>(dsm);
    if (vpath) __syncthreads();

    int g4 = lane >> 2, q4 = lane & 3;
    #pragma unroll
    for (int mt = 0; mt < 4; mt++) {
        int rl0 = wm * 64 + mt * 16 + g4;
        int row0 = r0 + rl0;
        int row1 = row0 + 8;
        float d0 = 1.f, d1 = 1.f;
        if (EPI == EPI_DIV) {
            d0 = 1.0f / den[(size_t)bz * denB + row0];
            d1 = 1.0f / den[(size_t)bz * denB + row1];
        }
        float rs0 = 0.f, rs1 = 0.f, rq0 = 0.f, rq1 = 0.f;
        #pragma unroll
        for (int nt = 0; nt < 4; nt++) {
            int lc   = wn * 32 + nt * 8 + q4 * 2;
            int colL = cSub + lc;
            int col  = c0 + lc;
            float v0 = c[mt][nt][0], v1 = c[mt][nt][1];
            float v2 = c[mt][nt][2], v3 = c[mt][nt][3];
            if (EPI == EPI_BIAS || EPI == EPI_FEAT || EPI == EPI_GELU ||
                EPI == EPI_BIAS_RES || EPI == EPI_QKV || EPI == EPI_OPROJ) {
                float2 bv = *reinterpret_cast<const float2*>(biasSel + colL);
                v0 += bv.x; v1 += bv.y; v2 += bv.x; v3 += bv.y;
            }
            if (EPI == EPI_FEAT || (EPI == EPI_QKV && seg < 2)) {
                v0 = (v0 > 0.f) ? (v0 + 1.f) : expf(v0);
                v1 = (v1 > 0.f) ? (v1 + 1.f) : expf(v1);
                v2 = (v2 > 0.f) ? (v2 + 1.f) : expf(v2);
                v3 = (v3 > 0.f) ? (v3 + 1.f) : expf(v3);
            }
            if (EPI == EPI_GELU) {
                v0 = gelu_exact(v0); v1 = gelu_exact(v1);
                v2 = gelu_exact(v2); v3 = gelu_exact(v3);
            }
            if (EPI == EPI_BIAS_RES || EPI == EPI_OPROJ) {
                const float* rp0 = res + (size_t)bz * sRes + (size_t)row0 * ldC + colL;
                const float* rp1 = res + (size_t)bz * sRes + (size_t)row1 * ldC + colL;
                float2 r0v = *reinterpret_cast<const float2*>(rp0);
                float2 r1v = *reinterpret_cast<const float2*>(rp1);
                v0 += r0v.x; v1 += r0v.y; v2 += r1v.x; v3 += r1v.y;
            }
            if (EPI == EPI_DIV) {
                v0 *= d0; v1 *= d0; v2 *= d1; v3 *= d1;
            }
            if (EPI == EPI_SCORE) {
                if (col     > row0) v0 = 0.f;
                if (col + 1 > row0) v1 = 0.f;
                if (col     > row1) v2 = 0.f;
                if (col + 1 > row1) v3 = 0.f;
                rs0 += v0 + v1; rs1 += v2 + v3;
            }
            if (EPI == EPI_OPROJ) {
                rs0 += v0 + v1;          rs1 += v2 + v3;
                rq0 += v0*v0 + v1*v1;    rq1 += v2*v2 + v3*v3;
            }
            if (vpath) {
                *reinterpret_cast<__half2*>(ts + rl0 * TSP + lc)       = __floats2half2_rn(v0, v1);
                *reinterpret_cast<__half2*>(ts + (rl0 + 8) * TSP + lc) = __floats2half2_rn(v2, v3);
            } else {
                st2(outSel + (size_t)row0 * ldC + colL, v0, v1);
                st2(outSel + (size_t)row1 * ldC + colL, v2, v3);
            }
        }
        if (EPI == EPI_SCORE) {
            atomicAdd(&den[(size_t)bz * denB + row0], rs0);
            atomicAdd(&den[(size_t)bz * denB + row1], rs1);
        }
        if constexpr (EPI == EPI_OPROJ) {
            #pragma unroll
            for (int o = 1; o < 4; o <<= 1) {
                rs0 += __shfl_xor_sync(0xffffffffu, rs0, o);
                rs1 += __shfl_xor_sync(0xffffffffu, rs1, o);
                rq0 += __shfl_xor_sync(0xffffffffu, rq0, o);
                rq1 += __shfl_xor_sync(0xffffffffu, rq1, o);
            }
            if (q4 == 0) {
                atomicAdd((float*)&C2[row0], rs0);
                atomicAdd((float*)&C2[row1], rs1);
                atomicAdd((float*)&C3[row0], rq0);
                atomicAdd((float*)&C3[row1], rq1);
            }
        }
    }

    if constexpr (EPI == EPI_QKV) {
        if (vpath) {
            __syncthreads();
            int cc = tid & 127, hh = tid >> 7;
            size_t b = (size_t)(r0 >> 11);
            int seqBase = r0 & 2047;
            __half* dst = C3 + b * (size_t)(Nq * Eq) + (size_t)(cSub + cc) * Nq + seqBase + hh * 64;
            #pragma unroll
            for (int i0 = 0; i0 < 64; i0 += 8) {
                __half tmp[8];
                #pragma unroll
                for (int k = 0; k < 8; k++)
                    tmp[k] = ts[(hh * 64 + i0 + k) * TSP + cc];
                *reinterpret_cast<uint4*>(dst + i0) = *reinterpret_cast<const uint4*>(tmp);
            }
        }
    }
}

// ---------------- launch ----------------
extern "C" void kernel_launch(void* const* d_in, const int* in_sizes, int n_in,
                              void* d_out, int out_size)
{
    const float* x     = (const float*)d_in[0];
    const float* q_w   = (const float*)d_in[1];
    const float* q_b   = (const float*)d_in[2];
    const float* k_w   = (const float*)d_in[3];
    const float* k_b   = (const float*)d_in[4];
    const float* v_w   = (const float*)d_in[5];
    const float* v_b   = (const float*)d_in[6];
    const float* o_w   = (const float*)d_in[7];
    const float* o_b   = (const float*)d_in[8];
    const float* ln1_g = (const float*)d_in[9];
    const float* ln1_b = (const float*)d_in[10];
    const float* ln2_g = (const float*)d_in[11];
    const float* ln2_b = (const float*)d_in[12];
    const float* w1    = (const float*)d_in[13];
    const float* b1    = (const float*)d_in[14];
    const float* w2    = (const float*)d_in[15];
    const float* b2    = (const float*)d_in[16];
    float* out = (float*)d_out;

    __half *xn, *Qp, *Kp, *Vt, *Pp, *attn, *xn2, *h;
    __half *qkvT, *oT, *w1T, *w2T;
    float *den, *s1, *s2, *x1;
    cudaGetSymbolAddress((void**)&xn,    g_xn);
    cudaGetSymbolAddress((void**)&Qp,    g_Q);
    cudaGetSymbolAddress((void**)&Kp,    g_K);
    cudaGetSymbolAddress((void**)&Vt,    g_Vt);
    cudaGetSymbolAddress((void**)&Pp,    g_P);
    cudaGetSymbolAddress((void**)&den,   g_den);
    cudaGetSymbolAddress((void**)&s1,    g_s1);
    cudaGetSymbolAddress((void**)&s2,    g_s2);
    cudaGetSymbolAddress((void**)&attn,  g_attn);
    cudaGetSymbolAddress((void**)&x1,    g_x1);
    cudaGetSymbolAddress((void**)&xn2,   g_xn2);
    cudaGetSymbolAddress((void**)&h,     g_h);
    cudaGetSymbolAddress((void**)&qkvT,  g_qkvT);
    cudaGetSymbolAddress((void**)&oT,    g_oT);
    cudaGetSymbolAddress((void**)&w1T,   g_w1T);
    cudaGetSymbolAddress((void**)&w2T,   g_w2T);

    cudaFuncSetAttribute(mm_kernel<EPI_QKV, 0, __half>,     cudaFuncAttributeMaxDynamicSharedMemorySize, MM_SMEM);
    cudaFuncSetAttribute(mm_kernel<EPI_SCORE, 1, __half>,   cudaFuncAttributeMaxDynamicSharedMemorySize, MM_SMEM);
    cudaFuncSetAttribute(mm_kernel<EPI_DIV, 2, __half>,     cudaFuncAttributeMaxDynamicSharedMemorySize, MM_SMEM);
    cudaFuncSetAttribute(mm_kernel<EPI_OPROJ, 0, float>,    cudaFuncAttributeMaxDynamicSharedMemorySize, MM_SMEM);
    cudaFuncSetAttribute(mm_kernel<EPI_BIAS_RES, 0, float>, cudaFuncAttributeMaxDynamicSharedMemorySize, MM_SMEM);
    cudaFuncSetAttribute(mm_kernel<EPI_GELU, 0, __half>,    cudaFuncAttributeMaxDynamicSharedMemorySize, MM_SMEM);

    // prep: all weight transposes + den/s1/s2 init + LN1 (one launch)
    prep_kernel<<<20496, dim3(32, 8)>>>(x, ln1_g, ln1_b, xn, den, s1, s2,
                                        q_w, k_w, v_w, o_w, w1, w2, qkvT, oT, w1T, w2T);

    // Fused Q/K/V projection; V written transposed to Vt in-epilogue
    mm_kernel<EPI_QKV, 0, __half><<<dim3(3*Eq/128, Mq/128, 1), 256, MM_SMEM>>>(
        xn, qkvT, Qp, Dq, Dq, Eq, Dq, 0, 0, 0, q_b, nullptr, 0, nullptr, 0,
        k_b, v_b, Kp, Vt);

    // scores: P = tril(Q K^T); den = rowsum + 1e-6
    mm_kernel<EPI_SCORE, 1, __half><<<dim3(Nq/128, Nq/128, Bq), 256, MM_SMEM>>>(
        Qp, Kp, Pp, Eq, Eq, Nq, Eq,
        (long long)Nq * Eq, (long long)Nq * Eq, (long long)Nq * Nq,
        nullptr, nullptr, 0, den, Nq);

    // attn = (P @ V) / den  (B operand = V^T, K limited per tile row, heavy-first)
    mm_kernel<EPI_DIV, 2, __half><<<dim3(Eq/128, Nq/128, Bq), 256, MM_SMEM>>>(
        Pp, Vt, attn, Nq, Nq, Eq, Nq,
        (long long)Nq * Nq, (long long)Nq * Eq, (long long)Nq * Eq,
        nullptr, nullptr, 0, den, Nq);

    // output projection + residual (fp32 out) + LN2 row stats via atomics
    mm_kernel<EPI_OPROJ, 0, float><<<dim3(Dq/128, Mq/128, 1), 256, MM_SMEM>>>(
        attn, oT, x1, Eq, Eq, Dq, Eq, 0, 0, 0, o_b, x, 0, nullptr, 0,
        nullptr, nullptr, s1, s2);

    // LN2 (stats precomputed) + FFN
    ln2s_kernel<<<Mq, 256>>>(x1, s1, s2, ln2_g, ln2_b, xn2);
    mm_kernel<EPI_GELU, 0, __half><<<dim3(Fq/128, Mq/128, 1), 256, MM_SMEM>>>(
        xn2, w1T, h, Dq, Dq, Fq, Dq, 0, 0, 0, b1, nullptr, 0, nullptr, 0);
    mm_kernel<EPI_BIAS_RES, 0, float><<<dim3(Dq/128, Mq/128, 1), 256, MM_SMEM>>>(
        h, w2T, out, Fq, Fq, Dq, Fq, 0, 0, 0, b2, x1, 0, nullptr, 0);
}

// round 11
// speedup vs baseline: 1.7461x; 1.0626x over previous
#include <cuda_runtime.h>
#include <cuda_fp16.h>
#include <math.h>
#include <stdint.h>

// Problem shapes (fixed)
#define Bq 2
#define Nq 2048
#define Dq 1024
#define Eq 2048
#define Fq 4096
#define Mq (Bq*Nq)   // 4096 tokens

// ---------------- device scratch (no cudaMalloc allowed) ----------------
__device__ __align__(1024) __half g_xn   [(size_t)Mq*Dq];
__device__ __align__(1024) __half g_Q    [(size_t)Mq*Eq];
__device__ __align__(1024) __half g_K    [(size_t)Mq*Eq];
__device__ __align__(1024) __half g_Vt   [(size_t)Mq*Eq];
__device__ __align__(1024) __half g_P    [(size_t)Bq*Nq*Nq];
__device__ __align__(1024) float  g_den  [Mq];
__device__ __align__(1024) float  g_s1   [Mq];
__device__ __align__(1024) float  g_s2   [Mq];
__device__ __align__(1024) __half g_attn [(size_t)Mq*Eq];
__device__ __align__(1024) float  g_x1   [(size_t)Mq*Dq];
__device__ __align__(1024) __half g_xn2  [(size_t)Mq*Dq];
__device__ __align__(1024) __half g_h    [(size_t)Mq*Fq];
__device__ __align__(1024) __half g_qkvT [(size_t)3*Eq*Dq];
__device__ __align__(1024) __half g_oT   [(size_t)Dq*Eq];
__device__ __align__(1024) __half g_w1T  [(size_t)Dq*Fq];
__device__ __align__(1024) __half g_w2T  [(size_t)Dq*Fq];
__device__ int g_cnt[192];
// counter bases
#define CQKV 0
#define CS   32
#define CPV  64
#define CO   96
#define CL   128
#define CF   160

// ---------------- helpers ----------------
__device__ __forceinline__ uint32_t smem_u32(const void* p) {
    uint32_t a;
    asm("{ .reg .u64 t; cvta.to.shared.u64 t, %1; cvt.u32.u64 %0, t; }" : "=r"(a) : "l"(p));
    return a;
}
__device__ __forceinline__ void cp16(uint32_t dst, const void* src) {
    asm volatile("cp.async.cg.shared.global [%0], [%1], 16;" :: "r"(dst), "l"(src) : "memory");
}
#define CP_COMMIT() asm volatile("cp.async.commit_group;" ::: "memory")
#define CP_WAIT1()  asm volatile("cp.async.wait_group 1;" ::: "memory")

__device__ __forceinline__ void ldsm4(uint32_t (&r)[4], uint32_t addr) {
    asm volatile("ldmatrix.sync.aligned.m8n8.x4.shared.b16 {%0,%1,%2,%3}, [%4];"
                 : "=r"(r[0]), "=r"(r[1]), "=r"(r[2]), "=r"(r[3]) : "r"(addr));
}
__device__ __forceinline__ void mma_f16(float (&c)[4], const uint32_t (&a)[4],
                                        uint32_t b0, uint32_t b1) {
    asm volatile("mma.sync.aligned.m16n8k16.row.col.f32.f16.f16.f32 "
                 "{%0,%1,%2,%3}, {%4,%5,%6,%7}, {%8,%9}, {%0,%1,%2,%3};"
                 : "+f"(c[0]), "+f"(c[1]), "+f"(c[2]), "+f"(c[3])
                 : "r"(a[0]), "r"(a[1]), "r"(a[2]), "r"(a[3]), "r"(b0), "r"(b1));
}
__device__ __forceinline__ void st2(float* p, float a, float b) {
    *reinterpret_cast<float2*>(p) = make_float2(a, b);
}
__device__ __forceinline__ void st2(__half* p, float a, float b) {
    *reinterpret_cast<__half2*>(p) = __floats2half2_rn(a, b);
}
__device__ __forceinline__ float gelu_exact(float v) {
    return 0.5f * v * (1.0f + erff(v * 0.70710678118654752f));
}

// spin-wait on counter (consumer) / signal (producer)
__device__ __forceinline__ void waitcnt(int idx, int target) {
    if (threadIdx.x == 0) {
        volatile int* p = &g_cnt[idx];
        while (*p < target) __nanosleep(100);
        __threadfence();
    }
    __syncthreads();
}
__device__ __forceinline__ void postcnt(int idx) {
    __syncthreads();
    if (threadIdx.x == 0) {
        __threadfence();
        atomicAdd(&g_cnt[idx], 1);
    }
}

// ---------------- GEMM mainloop (device fn): 128x128 CTA, 8 warps 64x32, 3-stage ----------------
__device__ __forceinline__ void gemm_main(const __half* __restrict__ Ab,
                                          const __half* __restrict__ Bb,
                                          int ldA, int ldB, int r0, int c0, int nc,
                                          char* dsm, float (&c)[4][4][4])
{
    uint32_t s0 = (smem_u32(dsm) + 1023u) & ~1023u;
    int tid = threadIdx.x;

    int lm = tid >> 1;
    int cbase = (tid & 1) * 4;
    const __half* gA = Ab + (size_t)(r0 + lm) * ldA + cbase * 8;
    const __half* gB = Bb + (size_t)(c0 + lm) * ldB + cbase * 8;
    uint32_t sw[4];
    #pragma unroll
    for (int i = 0; i < 4; i++)
        sw[i] = (uint32_t)lm * 128u + (uint32_t)(((cbase + i) ^ (lm & 7)) << 4);

    #pragma unroll
    for (int j = 0; j < 2; j++) {
        uint32_t aB = s0 + j * 32768, bB = aB + 16384;
        #pragma unroll
        for (int i = 0; i < 4; i++) {
            cp16(aB + sw[i], gA + j * 64 + i * 8);
            cp16(bB + sw[i], gB + j * 64 + i * 8);
        }
        CP_COMMIT();
    }

    int lane = tid & 31;
    int wm = (tid >> 5) & 1;
    int wn = tid >> 6;
    int aRow = wm * 64 + (lane & 15);
    int aHalf = lane >> 4;
    int bg = lane >> 3;
    int bRow = wn * 32 + ((bg >> 1) * 8) + (lane & 7);
    int bHalf = bg & 1;
    uint32_t aOff = (uint32_t)aRow * 128u;
    uint32_t bOff = (uint32_t)bRow * 128u;
    int aR7 = aRow & 7, bR7 = bRow & 7;

    #pragma unroll
    for (int mt = 0; mt < 4; mt++)
        #pragma unroll
        for (int nt = 0; nt < 4; nt++)
            #pragma unroll
            for (int k = 0; k < 4; k++) c[mt][nt][k] = 0.f;

    int s = 0;
    for (int i = 0; i < nc; i++) {
        CP_WAIT1();
        __syncthreads();
        {
            int j = i + 2;
            if (j < nc) {
                int st = s + 2; if (st >= 3) st -= 3;
                uint32_t aB2 = s0 + st * 32768, bB2 = aB2 + 16384;
                #pragma unroll
                for (int ii = 0; ii < 4; ii++) {
                    cp16(aB2 + sw[ii], gA + (size_t)j * 64 + ii * 8);
                    cp16(bB2 + sw[ii], gB + (size_t)j * 64 + ii * 8);
                }
            }
            CP_COMMIT();
        }
        uint32_t aB = s0 + s * 32768, bB = aB + 16384;
        #pragma unroll
        for (int ks = 0; ks < 4; ks++) {
            uint32_t a[4][4];
            #pragma unroll
            for (int mt = 0; mt < 4; mt++) {
                uint32_t ad = aB + aOff + (uint32_t)(mt * 16 * 128)
                            + (uint32_t)(((ks * 2 + aHalf) ^ aR7) << 4);
                ldsm4(a[mt], ad);
            }
            uint32_t b[8];
            #pragma unroll
            for (int np = 0; np < 2; np++) {
                uint32_t bd = bB + bOff + (uint32_t)(np * 16 * 128)
                            + (uint32_t)(((ks * 2 + bHalf) ^ bR7) << 4);
                uint32_t r[4];
                ldsm4(r, bd);
                b[np*4+0]=r[0]; b[np*4+1]=r[1]; b[np*4+2]=r[2]; b[np*4+3]=r[3];
            }
            #pragma unroll
            for (int mt = 0; mt < 4; mt++) {
                mma_f16(c[mt][0], a[mt], b[0], b[1]);
                mma_f16(c[mt][1], a[mt], b[2], b[3]);
                mma_f16(c[mt][2], a[mt], b[4], b[5]);
                mma_f16(c[mt][3], a[mt], b[6], b[7]);
            }
        }
        if (++s >= 3) s = 0;
    }
}

#define MM_SMEM (3 * 32768 + 1024)
#define TSP 132

// ---------------- prep: transposes + init + LN1 ----------------
__global__ __launch_bounds__(256)
void prep_kernel(const float* __restrict__ x, const float* __restrict__ ln1_g,
                 const float* __restrict__ ln1_b,
                 const float* __restrict__ q_w, const float* __restrict__ k_w,
                 const float* __restrict__ v_w, const float* __restrict__ o_w,
                 const float* __restrict__ w1,  const float* __restrict__ w2)
{
    int bid = blockIdx.x;
    if (bid < 16384) {
        __shared__ float t[32][33];
        const float* src; __half* dst; int R, C;
        if (bid < 6144) {
            int seg = bid >> 11; bid -= seg << 11;
            src = (seg == 0) ? q_w : (seg == 1) ? k_w : v_w;
            dst = g_qkvT + (size_t)seg * Eq * Dq;  R = Dq; C = Eq;
        } else if (bid < 8192)  { bid -= 6144;  src = o_w; dst = g_oT;  R = Eq; C = Dq; }
        else if (bid < 12288)   { bid -= 8192;  src = w1;  dst = g_w1T; R = Dq; C = Fq; }
        else                    { bid -= 12288; src = w2;  dst = g_w2T; R = Fq; C = Dq; }
        int tpr = C >> 5;
        int tx = bid % tpr, ty = bid / tpr;
        int c = tx * 32 + threadIdx.x;
        int r = ty * 32 + threadIdx.y;
        #pragma unroll
        for (int dy = 0; dy < 32; dy += 8)
            t[threadIdx.y + dy][threadIdx.x] = src[(size_t)(r + dy) * C + c];
        __syncthreads();
        int c2 = ty * 32 + threadIdx.x;
        int r2 = tx * 32 + threadIdx.y;
        #pragma unroll
        for (int dy = 0; dy < 32; dy += 8)
            dst[(size_t)(r2 + dy) * R + c2] = (__half)t[threadIdx.x][threadIdx.y + dy];
    } else if (bid < 16400) {
        int li = threadIdx.y * 32 + threadIdx.x;
        int idx = (bid - 16384) * 256 + li;
        g_den[idx] = 1e-6f; g_s1[idx] = 0.f; g_s2[idx] = 0.f;
        if (bid == 16384 && li < 192) g_cnt[li] = 0;
    } else {
        int row = bid - 16400;
        int t = threadIdx.y * 32 + threadIdx.x;
        const float4* xr = reinterpret_cast<const float4*>(x + (size_t)row * Dq);
        float4 v = xr[t];
        float s  = v.x + v.y + v.z + v.w;
        float s2r = v.x*v.x + v.y*v.y + v.z*v.z + v.w*v.w;
        __shared__ float rs[8], rs2[8];
        #pragma unroll
        for (int o = 16; o > 0; o >>= 1) {
            s   += __shfl_down_sync(0xffffffffu, s,   o);
            s2r += __shfl_down_sync(0xffffffffu, s2r, o);
        }
        if ((t & 31) == 0) { rs[t >> 5] = s; rs2[t >> 5] = s2r; }
        __syncthreads();
        float ssum = 0.f, ssum2 = 0.f;
        #pragma unroll
        for (int i = 0; i < 8; i++) { ssum += rs[i]; ssum2 += rs2[i]; }
        float mu   = ssum * (1.0f / Dq);
        float var  = ssum2 * (1.0f / Dq) - mu * mu;
        float rstd = rsqrtf(var + 1e-5f);
        float4 gg = reinterpret_cast<const float4*>(ln1_g)[t];
        float4 bb = reinterpret_cast<const float4*>(ln1_b)[t];
        __half2 h01 = __floats2half2_rn((v.x - mu) * rstd * gg.x + bb.x,
                                        (v.y - mu) * rstd * gg.y + bb.y);
        __half2 h23 = __floats2half2_rn((v.z - mu) * rstd * gg.z + bb.z,
                                        (v.w - mu) * rstd * gg.w + bb.w);
        __half2* yp = reinterpret_cast<__half2*>(g_xn + (size_t)row * Dq);
        yp[t * 2]     = h01;
        yp[t * 2 + 1] = h23;
    }
}

// ---------------- mega kernel: entire layer after prep, block-level dataflow ----------------
__global__ __launch_bounds__(256, 2)
void mega_kernel(const float* __restrict__ x,
                 const float* __restrict__ q_b, const float* __restrict__ k_b,
                 const float* __restrict__ v_b, const float* __restrict__ o_b,
                 const float* __restrict__ ln2_g, const float* __restrict__ ln2_b,
                 const float* __restrict__ b1, const float* __restrict__ b2,
                 float* __restrict__ out)
{
    extern __shared__ char dsm[];
    int bid = blockIdx.x;
    int tid = threadIdx.x;
    int lane = tid & 31, wm = (tid >> 5) & 1, wn = tid >> 6;
    int g4 = lane >> 2, q4 = lane & 3;

    if (bid < 1536) {
        // ---- QKV: [4096,1024] x [6144,1024]^T ----
        int rb = bid / 48, ctg = bid % 48;
        int r0 = rb * 128, c0 = ctg * 128;
        float acc[4][4][4];
        gemm_main(g_xn, g_qkvT, Dq, Dq, r0, c0, Dq >> 6, dsm, acc);

        int seg = c0 >> 11;
        const float* biasSel = (seg == 0) ? q_b : (seg == 1) ? k_b : v_b;
        __half* outSel = (seg == 0) ? g_Q : g_K;
        int cSub = c0 - (seg << 11);
        bool vpath = (seg == 2);
        __half* ts = reinterpret_cast<__half*>(dsm);
        if (vpath) __syncthreads();

        #pragma unroll
        for (int mt = 0; mt < 4; mt++) {
            int rl0 = wm * 64 + mt * 16 + g4;
            int row0 = r0 + rl0, row1 = row0 + 8;
            #pragma unroll
            for (int nt = 0; nt < 4; nt++) {
                int lc = wn * 32 + nt * 8 + q4 * 2;
                int colL = cSub + lc;
                float2 bv = *reinterpret_cast<const float2*>(biasSel + colL);
                float v0 = acc[mt][nt][0] + bv.x, v1 = acc[mt][nt][1] + bv.y;
                float v2 = acc[mt][nt][2] + bv.x, v3 = acc[mt][nt][3] + bv.y;
                if (seg < 2) {
                    v0 = (v0 > 0.f) ? (v0 + 1.f) : expf(v0);
                    v1 = (v1 > 0.f) ? (v1 + 1.f) : expf(v1);
                    v2 = (v2 > 0.f) ? (v2 + 1.f) : expf(v2);
                    v3 = (v3 > 0.f) ? (v3 + 1.f) : expf(v3);
                }
                if (vpath) {
                    *reinterpret_cast<__half2*>(ts + rl0 * TSP + lc)       = __floats2half2_rn(v0, v1);
                    *reinterpret_cast<__half2*>(ts + (rl0 + 8) * TSP + lc) = __floats2half2_rn(v2, v3);
                } else {
                    st2(outSel + (size_t)row0 * Eq + colL, v0, v1);
                    st2(outSel + (size_t)row1 * Eq + colL, v2, v3);
                }
            }
        }
        if (vpath) {
            __syncthreads();
            int cc = tid & 127, hh = tid >> 7;
            size_t b = (size_t)(r0 >> 11);
            int seqBase = r0 & 2047;
            __half* dst = g_Vt + b * (size_t)(Nq * Eq) + (size_t)(cSub + cc) * Nq + seqBase + hh * 64;
            #pragma unroll
            for (int i0 = 0; i0 < 64; i0 += 8) {
                __half tmp[8];
                #pragma unroll
                for (int k = 0; k < 8; k++)
                    tmp[k] = ts[(hh * 64 + i0 + k) * TSP + cc];
                *reinterpret_cast<uint4*>(dst + i0) = *reinterpret_cast<const uint4*>(tmp);
            }
        }
        postcnt(CQKV + rb);

    } else if (bid < 2048) {
        // ---- scores: P = tril(Q K^T), den += rowsum ----
        int i = bid - 1536;
        int rtg = i >> 4;                 // global row-block 0..31
        int bz = rtg >> 4, rt = rtg & 15, ct = i & 15;
        if (ct > rt) return;
        waitcnt(CQKV + rtg, 48);
        waitcnt(CQKV + bz * 16 + ct, 48);
        int r0 = rt * 128, c0 = ct * 128;
        const __half* Ab = g_Q + (size_t)bz * Nq * Eq;
        const __half* Bb = g_K + (size_t)bz * Nq * Eq;
        float acc[4][4][4];
        gemm_main(Ab, Bb, Eq, Eq, r0, c0, Eq >> 6, dsm, acc);

        __half* Cb = g_P + (size_t)bz * Nq * Nq;
        float* denb = g_den + (size_t)bz * Nq;
        #pragma unroll
        for (int mt = 0; mt < 4; mt++) {
            int row0 = r0 + wm * 64 + mt * 16 + g4, row1 = row0 + 8;
            float rs0 = 0.f, rs1 = 0.f;
            #pragma unroll
            for (int nt = 0; nt < 4; nt++) {
                int col = c0 + wn * 32 + nt * 8 + q4 * 2;
                float v0 = acc[mt][nt][0], v1 = acc[mt][nt][1];
                float v2 = acc[mt][nt][2], v3 = acc[mt][nt][3];
                if (col     > row0) v0 = 0.f;
                if (col + 1 > row0) v1 = 0.f;
                if (col     > row1) v2 = 0.f;
                if (col + 1 > row1) v3 = 0.f;
                rs0 += v0 + v1; rs1 += v2 + v3;
                st2(Cb + (size_t)row0 * Nq + col, v0, v1);
                st2(Cb + (size_t)row1 * Nq + col, v2, v3);
            }
            atomicAdd(&denb[row0], rs0);
            atomicAdd(&denb[row1], rs1);
        }
        postcnt(CS + rtg);

    } else if (bid < 2560) {
        // ---- PV: attn = (P @ V) / den ----
        int i = bid - 2048;
        int rtg = i >> 4;
        int bz = rtg >> 4, rt = rtg & 15, ctE = i & 15;
        waitcnt(CS + rtg, rt + 1);
        int r0 = rt * 128, c0 = ctE * 128;
        int nc = (r0 + 128) >> 6;
        const __half* Ab = g_P + (size_t)bz * Nq * Nq;
        const __half* Bb = g_Vt + (size_t)bz * Nq * Eq;
        float acc[4][4][4];
        gemm_main(Ab, Bb, Nq, Nq, r0, c0, nc, dsm, acc);

        __half* Cb = g_attn + (size_t)bz * Nq * Eq;
        const float* denb = g_den + (size_t)bz * Nq;
        #pragma unroll
        for (int mt = 0; mt < 4; mt++) {
            int row0 = r0 + wm * 64 + mt * 16 + g4, row1 = row0 + 8;
            float d0 = 1.0f / denb[row0], d1 = 1.0f / denb[row1];
            #pragma unroll
            for (int nt = 0; nt < 4; nt++) {
                int col = c0 + wn * 32 + nt * 8 + q4 * 2;
                st2(Cb + (size_t)row0 * Eq + col, acc[mt][nt][0] * d0, acc[mt][nt][1] * d0);
                st2(Cb + (size_t)row1 * Eq + col, acc[mt][nt][2] * d1, acc[mt][nt][3] * d1);
            }
        }
        postcnt(CPV + rtg);

    } else if (bid < 2816) {
        // ---- Oproj: x1 = attn @ oT + o_b + x; s1/s2 row stats ----
        int i = bid - 2560;
        int mrb = i >> 3, ct = i & 7;
        waitcnt(CPV + mrb, 16);
        int r0 = mrb * 128, c0 = ct * 128;
        float acc[4][4][4];
        gemm_main(g_attn, g_oT, Eq, Eq, r0, c0, Eq >> 6, dsm, acc);

        #pragma unroll
        for (int mt = 0; mt < 4; mt++) {
            int row0 = r0 + wm * 64 + mt * 16 + g4, row1 = row0 + 8;
            float rs0 = 0.f, rs1 = 0.f, rq0 = 0.f, rq1 = 0.f;
            #pragma unroll
            for (int nt = 0; nt < 4; nt++) {
                int col = c0 + wn * 32 + nt * 8 + q4 * 2;
                float2 bv = *reinterpret_cast<const float2*>(o_b + col);
                float2 r0v = *reinterpret_cast<const float2*>(x + (size_t)row0 * Dq + col);
                float2 r1v = *reinterpret_cast<const float2*>(x + (size_t)row1 * Dq + col);
                float v0 = acc[mt][nt][0] + bv.x + r0v.x;
                float v1 = acc[mt][nt][1] + bv.y + r0v.y;
                float v2 = acc[mt][nt][2] + bv.x + r1v.x;
                float v3 = acc[mt][nt][3] + bv.y + r1v.y;
                rs0 += v0 + v1;        rs1 += v2 + v3;
                rq0 += v0*v0 + v1*v1;  rq1 += v2*v2 + v3*v3;
                st2(g_x1 + (size_t)row0 * Dq + col, v0, v1);
                st2(g_x1 + (size_t)row1 * Dq + col, v2, v3);
            }
            #pragma unroll
            for (int o = 1; o < 4; o <<= 1) {
                rs0 += __shfl_xor_sync(0xffffffffu, rs0, o);
                rs1 += __shfl_xor_sync(0xffffffffu, rs1, o);
                rq0 += __shfl_xor_sync(0xffffffffu, rq0, o);
                rq1 += __shfl_xor_sync(0xffffffffu, rq1, o);
            }
            if (q4 == 0) {
                atomicAdd(&g_s1[row0], rs0);
                atomicAdd(&g_s1[row1], rs1);
                atomicAdd(&g_s2[row0], rq0);
                atomicAdd(&g_s2[row1], rq1);
            }
        }
        postcnt(CO + mrb);

    } else if (bid < 2848) {
        // ---- LN2 (stats precomputed): xn2 = norm(x1) ----
        int rb = bid - 2816;
        waitcnt(CO + rb, 8);
        int t2 = tid >> 1, half = tid & 1;
        int row = rb * 128 + t2;
        float mu   = g_s1[row] * (1.0f / Dq);
        float var  = g_s2[row] * (1.0f / Dq) - mu * mu;
        float rstd = rsqrtf(var + 1e-5f);
        const float4* xp = reinterpret_cast<const float4*>(g_x1 + (size_t)row * Dq + half * 512);
        const float4* gp = reinterpret_cast<const float4*>(ln2_g) + half * 128;
        const float4* bp = reinterpret_cast<const float4*>(ln2_b) + half * 128;
        __half2* yp = reinterpret_cast<__half2*>(g_xn2 + (size_t)row * Dq + half * 512);
        for (int j = 0; j < 128; j++) {
            float4 v = xp[j];
            float4 gg = gp[j];
            float4 bb = bp[j];
            yp[j * 2]     = __floats2half2_rn((v.x - mu) * rstd * gg.x + bb.x,
                                              (v.y - mu) * rstd * gg.y + bb.y);
            yp[j * 2 + 1] = __floats2half2_rn((v.z - mu) * rstd * gg.z + bb.z,
                                              (v.w - mu) * rstd * gg.w + bb.w);
        }
        postcnt(CL + rb);

    } else if (bid < 3872) {
        // ---- FFN1: h = gelu(xn2 @ w1T + b1) ----
        int i = bid - 2848;
        int mrb = i >> 5, ct = i & 31;
        waitcnt(CL + mrb, 1);
        int r0 = mrb * 128, c0 = ct * 128;
        float acc[4][4][4];
        gemm_main(g_xn2, g_w1T, Dq, Dq, r0, c0, Dq >> 6, dsm, acc);

        #pragma unroll
        for (int mt = 0; mt < 4; mt++) {
            int row0 = r0 + wm * 64 + mt * 16 + g4, row1 = row0 + 8;
            #pragma unroll
            for (int nt = 0; nt < 4; nt++) {
                int col = c0 + wn * 32 + nt * 8 + q4 * 2;
                float2 bv = *reinterpret_cast<const float2*>(b1 + col);
                float v0 = gelu_exact(acc[mt][nt][0] + bv.x);
                float v1 = gelu_exact(acc[mt][nt][1] + bv.y);
                float v2 = gelu_exact(acc[mt][nt][2] + bv.x);
                float v3 = gelu_exact(acc[mt][nt][3] + bv.y);
                st2(g_h + (size_t)row0 * Fq + col, v0, v1);
                st2(g_h + (size_t)row1 * Fq + col, v2, v3);
            }
        }
        postcnt(CF + mrb);

    } else {
        // ---- FFN2: out = h @ w2T + b2 + x1 ----
        int i = bid - 3872;
        int mrb = i >> 3, ct = i & 7;
        waitcnt(CF + mrb, 32);
        int r0 = mrb * 128, c0 = ct * 128;
        float acc[4][4][4];
        gemm_main(g_h, g_w2T, Fq, Fq, r0, c0, Fq >> 6, dsm, acc);

        #pragma unroll
        for (int mt = 0; mt < 4; mt++) {
            int row0 = r0 + wm * 64 + mt * 16 + g4, row1 = row0 + 8;
            #pragma unroll
            for (int nt = 0; nt < 4; nt++) {
                int col = c0 + wn * 32 + nt * 8 + q4 * 2;
                float2 bv = *reinterpret_cast<const float2*>(b2 + col);
                float2 r0v = *reinterpret_cast<const float2*>(g_x1 + (size_t)row0 * Dq + col);
                float2 r1v = *reinterpret_cast<const float2*>(g_x1 + (size_t)row1 * Dq + col);
                st2(out + (size_t)row0 * Dq + col, acc[mt][nt][0] + bv.x + r0v.x,
                                                   acc[mt][nt][1] + bv.y + r0v.y);
                st2(out + (size_t)row1 * Dq + col, acc[mt][nt][2] + bv.x + r1v.x,
                                                   acc[mt][nt][3] + bv.y + r1v.y);
            }
        }
    }
}

// ---------------- launch ----------------
extern "C" void kernel_launch(void* const* d_in, const int* in_sizes, int n_in,
                              void* d_out, int out_size)
{
    const float* x     = (const float*)d_in[0];
    const float* q_w   = (const float*)d_in[1];
    const float* q_b   = (const float*)d_in[2];
    const float* k_w   = (const float*)d_in[3];
    const float* k_b   = (const float*)d_in[4];
    const float* v_w   = (const float*)d_in[5];
    const float* v_b   = (const float*)d_in[6];
    const float* o_w   = (const float*)d_in[7];
    const float* o_b   = (const float*)d_in[8];
    const float* ln1_g = (const float*)d_in[9];
    const float* ln1_b = (const float*)d_in[10];
    const float* ln2_g = (const float*)d_in[11];
    const float* ln2_b = (const float*)d_in[12];
    const float* w1    = (const float*)d_in[13];
    const float* b1    = (const float*)d_in[14];
    const float* w2    = (const float*)d_in[15];
    const float* b2    = (const float*)d_in[16];
    float* out = (float*)d_out;

    cudaFuncSetAttribute(mega_kernel, cudaFuncAttributeMaxDynamicSharedMemorySize, MM_SMEM);

    // prep: weight transposes + den/s1/s2/counter init + LN1
    prep_kernel<<<20496, dim3(32, 8)>>>(x, ln1_g, ln1_b, q_w, k_w, v_w, o_w, w1, w2);

    // everything else in one launch with block-level dataflow
    mega_kernel<<<4128, 256, MM_SMEM>>>(x, q_b, k_b, v_b, o_b, ln2_g, ln2_b, b1, b2, out);
}